// round 1
// baseline (speedup 1.0000x reference)
#include <cuda_runtime.h>
#include <math.h>

#define Bz  32
#define Sz  48
#define Vz  10000
#define CVz 9600
#define Hz  768
#define NHz 12
#define NLz 12
#define Gz  32
#define HDz 64
#define CPG (Hz/Gz)   // 24

// ------------------------- scratch (no allocation allowed) -------------------------
__device__ float g_h  [Bz*Sz*Hz];
__device__ float g_x  [Bz*Sz*Hz];
__device__ float g_qkv[Bz*Sz*3*Hz];
__device__ float g_a  [Bz*Sz*Hz];
__device__ float g_mlp[Bz*Sz*4*Hz];
__device__ float g_cat[Bz*(Sz-1)*2*Hz];
__device__ float g_a1 [Bz*(Sz-1)*2*Hz];

// ------------------------- sparse embedding + pos embed -------------------------
// h[b,s,:] = sum_v visits[b,s,v]*vis_embed[v,:] + pos_embed[s,:]
// visits is ~1% dense -> deterministic ballot-compaction gather.
__global__ void embed_kernel(const float* __restrict__ visits,
                             const float* __restrict__ vemb,
                             const float* __restrict__ pemb,
                             float* __restrict__ out)
{
    int row = blockIdx.x;            // b*Sz + s
    int s   = row % Sz;
    const float* vrow = visits + (size_t)row * Vz;
    int t = threadIdx.x;             // 256 threads
    float acc[3];
#pragma unroll
    for (int i = 0; i < 3; i++) acc[i] = pemb[s*Hz + t + i*256];

    __shared__ int   s_idx[256];
    __shared__ float s_val[256];
    __shared__ int   wcnt[8];

    int lane = t & 31, w = t >> 5;

    for (int base = 0; base < Vz; base += 256) {
        __syncthreads();
        int v = base + t;
        float val = (v < Vz) ? vrow[v] : 0.f;
        unsigned m = __ballot_sync(0xffffffffu, val != 0.f);
        if (lane == 0) wcnt[w] = __popc(m);
        __syncthreads();
        int off = 0;
#pragma unroll
        for (int i = 0; i < 8; i++) { if (i < w) off += wcnt[i]; }
        int cnt = 0;
#pragma unroll
        for (int i = 0; i < 8; i++) cnt += wcnt[i];
        if (val != 0.f) {
            int p = off + __popc(m & ((1u << lane) - 1u));
            s_idx[p] = v; s_val[p] = val;
        }
        __syncthreads();
        for (int j = 0; j < cnt; j++) {
            const float* er = vemb + (size_t)s_idx[j] * Hz;
            float vv = s_val[j];
#pragma unroll
            for (int i = 0; i < 3; i++) acc[i] += vv * er[t + i*256];
        }
    }
    float* orow = out + (size_t)row * Hz;
#pragma unroll
    for (int i = 0; i < 3; i++) orow[t + i*256] = acc[i];
}

// ------------------------- group norm (stats over S x H/G per (b,g)) -------------------------
__global__ void groupnorm_kernel(const float* __restrict__ in, float* __restrict__ out,
                                 const float* __restrict__ w, const float* __restrict__ b)
{
    int bg = blockIdx.x;
    int bt = bg / Gz, g = bg % Gz;
    int t = threadIdx.x;             // 128 threads
    const int NELEM = Sz * CPG;      // 1152
    float sum = 0.f, sq = 0.f;
    for (int idx = t; idx < NELEM; idx += 128) {
        int s = idx / CPG, c = idx % CPG;
        float v = in[((size_t)bt*Sz + s)*Hz + g*CPG + c];
        sum += v; sq += v*v;
    }
    __shared__ float r1[128], r2[128];
    r1[t] = sum; r2[t] = sq; __syncthreads();
    for (int o = 64; o > 0; o >>= 1) {
        if (t < o) { r1[t] += r1[t+o]; r2[t] += r2[t+o]; }
        __syncthreads();
    }
    float mean = r1[0] / NELEM;
    float var  = r2[0] / NELEM - mean*mean;
    float inv  = rsqrtf(var + 1e-5f);
    for (int idx = t; idx < NELEM; idx += 128) {
        int s = idx / CPG, c = idx % CPG;
        int ch = g*CPG + c;
        size_t off = ((size_t)bt*Sz + s)*Hz + ch;
        out[off] = (in[off] - mean) * inv * w[ch] + b[ch];
    }
}

// ------------------------- SGEMM: C = act(A[M,K] @ W[K,N] + bias (+res)) -------------------------
// mode bits: 1=bias, 2=res-add, 4=gelu, 8=relu, 16=sigmoid
__global__ __launch_bounds__(256, 2)
void sgemm_kernel(const float* __restrict__ A, const float* __restrict__ W,
                  const float* __restrict__ bias, const float* __restrict__ res,
                  float* __restrict__ C, int M, int N, int K, int mode)
{
    __shared__ float sA[8][132];
    __shared__ float sB[8][132];
    int t  = threadIdx.x;
    int bm = blockIdx.y * 128;
    int bn = blockIdx.x * 128;
    int arow = t >> 1,  acol = (t & 1) * 4;
    int brow = t >> 5,  bcol = (t & 31) * 4;
    int ty = t >> 4, tx = t & 15;
    int row0 = ty * 8, col0 = tx * 8;
    float acc[8][8] = {};

    bool aval = (bm + arow) < M;
    const float* Aptr = A + (size_t)(bm + arow) * K + acol;
    const float* Wptr = W + (size_t)brow * N + bn + bcol;

    for (int k0 = 0; k0 < K; k0 += 8) {
        float4 a4 = aval ? *(const float4*)(Aptr + k0) : make_float4(0.f,0.f,0.f,0.f);
        float4 b4 = *(const float4*)(Wptr + (size_t)k0 * N);
        sA[acol+0][arow] = a4.x; sA[acol+1][arow] = a4.y;
        sA[acol+2][arow] = a4.z; sA[acol+3][arow] = a4.w;
        *(float4*)&sB[brow][bcol] = b4;
        __syncthreads();
#pragma unroll
        for (int kk = 0; kk < 8; kk++) {
            float ra[8], rb[8];
#pragma unroll
            for (int i = 0; i < 8; i++) ra[i] = sA[kk][row0+i];
#pragma unroll
            for (int j = 0; j < 8; j++) rb[j] = sB[kk][col0+j];
#pragma unroll
            for (int i = 0; i < 8; i++)
#pragma unroll
                for (int j = 0; j < 8; j++) acc[i][j] += ra[i]*rb[j];
        }
        __syncthreads();
    }
#pragma unroll
    for (int i = 0; i < 8; i++) {
        int gr = bm + row0 + i;
        if (gr >= M) break;
#pragma unroll
        for (int j = 0; j < 8; j++) {
            int gc = bn + col0 + j;
            float v = acc[i][j];
            if (mode & 1)  v += bias[gc];
            if (mode & 2)  v += res[(size_t)gr*N + gc];
            if (mode & 4) { float x = v;
                v = 0.5f*x*(1.f + tanhf(0.7978845608028654f*(x + 0.044715f*x*x*x))); }
            if (mode & 8)  v = fmaxf(v, 0.f);
            if (mode & 16) v = 1.f/(1.f + expf(-v));
            C[(size_t)gr*N + gc] = v;
        }
    }
}

// ------------- masked transposed GEMM: C = act(A[M,K] @ (tril-masked W[N,K])^T + bias) -------------
// element W[n,k] kept iff k <= n  (tril mask of the reference head)
__global__ __launch_bounds__(256, 2)
void sgemm_t_kernel(const float* __restrict__ A, const float* __restrict__ Wr,
                    const float* __restrict__ bias,
                    float* __restrict__ C, int M, int N, int K, int mode)
{
    __shared__ float sA[8][132];
    __shared__ float sB[8][132];
    int t  = threadIdx.x;
    int bm = blockIdx.y * 128;
    int bn = blockIdx.x * 128;
    int arow = t >> 1, acol = (t & 1) * 4;
    int bcolc = t >> 1, brow4 = (t & 1) * 4;   // n-within-tile, k-within-tile
    int ty = t >> 4, tx = t & 15;
    int row0 = ty * 8, col0 = tx * 8;
    float acc[8][8] = {};

    bool aval = (bm + arow) < M;
    const float* Aptr = A + (size_t)(bm + arow) * K + acol;
    int gn = bn + bcolc;
    const float* Wt = Wr + (size_t)gn * K + brow4;

    for (int k0 = 0; k0 < K; k0 += 8) {
        float4 a4 = aval ? *(const float4*)(Aptr + k0) : make_float4(0.f,0.f,0.f,0.f);
        float4 b4 = *(const float4*)(Wt + k0);
        int kg = k0 + brow4;
        if (kg + 0 > gn) b4.x = 0.f;
        if (kg + 1 > gn) b4.y = 0.f;
        if (kg + 2 > gn) b4.z = 0.f;
        if (kg + 3 > gn) b4.w = 0.f;
        sA[acol+0][arow] = a4.x; sA[acol+1][arow] = a4.y;
        sA[acol+2][arow] = a4.z; sA[acol+3][arow] = a4.w;
        sB[brow4+0][bcolc] = b4.x; sB[brow4+1][bcolc] = b4.y;
        sB[brow4+2][bcolc] = b4.z; sB[brow4+3][bcolc] = b4.w;
        __syncthreads();
#pragma unroll
        for (int kk = 0; kk < 8; kk++) {
            float ra[8], rb[8];
#pragma unroll
            for (int i = 0; i < 8; i++) ra[i] = sA[kk][row0+i];
#pragma unroll
            for (int j = 0; j < 8; j++) rb[j] = sB[kk][col0+j];
#pragma unroll
            for (int i = 0; i < 8; i++)
#pragma unroll
                for (int j = 0; j < 8; j++) acc[i][j] += ra[i]*rb[j];
        }
        __syncthreads();
    }
#pragma unroll
    for (int i = 0; i < 8; i++) {
        int gr = bm + row0 + i;
        if (gr >= M) break;
#pragma unroll
        for (int j = 0; j < 8; j++) {
            int gc = bn + col0 + j;
            float v = acc[i][j];
            if (mode & 1)  v += bias[gc];
            if (mode & 8)  v = fmaxf(v, 0.f);
            if (mode & 16) v = 1.f/(1.f + expf(-v));
            C[(size_t)gr*N + gc] = v;
        }
    }
}

// ------------------------- attention: one CTA per (batch, head) -------------------------
__global__ void attn_kernel(const float* __restrict__ qkv, float* __restrict__ out)
{
    int bh = blockIdx.x;
    int b = bh / NHz, hd = bh % NHz;
    __shared__ float sq[Sz][HDz], sk[Sz][HDz], sv[Sz][HDz];
    __shared__ float sc[Sz][Sz+1];
    int t = threadIdx.x;   // 128

    const float* base = qkv + (size_t)b * Sz * (3*Hz);
    for (int idx = t; idx < Sz*HDz; idx += 128) {
        int s = idx / HDz, d = idx % HDz;
        size_t o = (size_t)s * (3*Hz) + hd*HDz + d;
        sq[s][d] = base[o];
        sk[s][d] = base[o + Hz];
        sv[s][d] = base[o + 2*Hz];
    }
    __syncthreads();
    for (int idx = t; idx < Sz*Sz; idx += 128) {
        int i = idx / Sz, j = idx % Sz;
        float a = -1e10f;
        if (j <= i) {
            a = 0.f;
#pragma unroll
            for (int d = 0; d < HDz; d++) a += sq[i][d]*sk[j][d];
            a *= 0.125f;   // 1/sqrt(64)
        }
        sc[i][j] = a;
    }
    __syncthreads();
    if (t < Sz) {
        int i = t;
        float mx = -1e30f;
        for (int j = 0; j <= i; j++) mx = fmaxf(mx, sc[i][j]);
        float sum = 0.f;
        for (int j = 0; j < Sz; j++) { float e = expf(sc[i][j]-mx); sc[i][j] = e; sum += e; }
        float inv = 1.f/sum;
        for (int j = 0; j < Sz; j++) sc[i][j] *= inv;
    }
    __syncthreads();
    float* ob = out + (size_t)b * Sz * Hz + hd*HDz;
    for (int idx = t; idx < Sz*HDz; idx += 128) {
        int i = idx / HDz, d = idx % HDz;
        float a = 0.f;
#pragma unroll
        for (int j = 0; j < Sz; j++) a += sc[i][j]*sv[j][d];
        ob[(size_t)i*Hz + d] = a;
    }
}

// ------------------------- concat [h[:, :-1], h[:, 1:]] -------------------------
__global__ void concat_kernel(const float* __restrict__ x, float* __restrict__ cat)
{
    int idx = blockIdx.x * 256 + threadIdx.x;
    const int total = Bz*(Sz-1)*2*Hz;
    if (idx >= total) return;
    int c  = idx % (2*Hz);
    int bt = idx / (2*Hz);
    int tp = bt % (Sz-1), b = bt / (Sz-1);
    float v;
    if (c < Hz) v = x[((size_t)b*Sz + tp)*Hz + c];
    else        v = x[((size_t)b*Sz + tp + 1)*Hz + (c - Hz)];
    cat[idx] = v;
}

// ------------------------- launch -------------------------
extern "C" void kernel_launch(void* const* d_in, const int* in_sizes, int n_in,
                              void* d_out, int out_size)
{
    const float* visits = (const float*)d_in[0];
    const float* vemb   = (const float*)d_in[1];
    const float* pemb   = (const float*)d_in[2];
    const float* ln1w   = (const float*)d_in[3];
    const float* ln1b   = (const float*)d_in[4];
    const float* attnw  = (const float*)d_in[5];
    const float* attnb  = (const float*)d_in[6];
    const float* projw  = (const float*)d_in[7];
    const float* projb  = (const float*)d_in[8];
    const float* ln2w   = (const float*)d_in[9];
    const float* ln2b   = (const float*)d_in[10];
    const float* fcw    = (const float*)d_in[11];
    const float* fcb    = (const float*)d_in[12];
    const float* mprojw = (const float*)d_in[13];
    const float* mprojb = (const float*)d_in[14];
    const float* lnfw   = (const float*)d_in[15];
    const float* lnfb   = (const float*)d_in[16];
    const float* a1w    = (const float*)d_in[17];
    const float* a1b    = (const float*)d_in[18];
    const float* a2w    = (const float*)d_in[19];
    const float* a2b    = (const float*)d_in[20];
    float* out = (float*)d_out;

    float *ph, *px, *pqkv, *pa, *pmlp, *pcat, *pa1;
    cudaGetSymbolAddress((void**)&ph,   g_h);
    cudaGetSymbolAddress((void**)&px,   g_x);
    cudaGetSymbolAddress((void**)&pqkv, g_qkv);
    cudaGetSymbolAddress((void**)&pa,   g_a);
    cudaGetSymbolAddress((void**)&pmlp, g_mlp);
    cudaGetSymbolAddress((void**)&pcat, g_cat);
    cudaGetSymbolAddress((void**)&pa1,  g_a1);

    const int M = Bz * Sz;   // 1536

    embed_kernel<<<Bz*Sz, 256>>>(visits, vemb, pemb, ph);

    for (int l = 0; l < NLz; l++) {
        groupnorm_kernel<<<Bz*Gz, 128>>>(ph, px, ln1w + l*Hz, ln1b + l*Hz);
        sgemm_kernel<<<dim3(3*Hz/128, M/128), 256>>>(
            px, attnw + (size_t)l*Hz*3*Hz, attnb + (size_t)l*3*Hz, nullptr,
            pqkv, M, 3*Hz, Hz, 1);
        attn_kernel<<<Bz*NHz, 128>>>(pqkv, pa);
        sgemm_kernel<<<dim3(Hz/128, M/128), 256>>>(
            pa, projw + (size_t)l*Hz*Hz, projb + (size_t)l*Hz, ph,
            ph, M, Hz, Hz, 1|2);
        groupnorm_kernel<<<Bz*Gz, 128>>>(ph, px, ln2w + l*Hz, ln2b + l*Hz);
        sgemm_kernel<<<dim3(4*Hz/128, M/128), 256>>>(
            px, fcw + (size_t)l*Hz*4*Hz, fcb + (size_t)l*4*Hz, nullptr,
            pmlp, M, 4*Hz, Hz, 1|4);
        sgemm_kernel<<<dim3(Hz/128, M/128), 256>>>(
            pmlp, mprojw + (size_t)l*4*Hz*Hz, mprojb + (size_t)l*Hz, ph,
            ph, M, Hz, 4*Hz, 1|2);
    }

    groupnorm_kernel<<<Bz*Gz, 128>>>(ph, px, lnfw, lnfb);

    const int Mh = Bz * (Sz - 1);  // 1504
    concat_kernel<<<(Mh*2*Hz + 255)/256, 256>>>(px, pcat);
    sgemm_t_kernel<<<dim3(2*Hz/128, (Mh + 127)/128), 256>>>(
        pcat, a1w, a1b, pa1, Mh, 2*Hz, 2*Hz, 1|8);
    sgemm_t_kernel<<<dim3(CVz/128, (Mh + 127)/128), 256>>>(
        pa1, a2w, a2b, out, Mh, CVz, 2*Hz, 1|16);
}

// round 2
// speedup vs baseline: 1.8686x; 1.8686x over previous
#include <cuda_runtime.h>
#include <math.h>
#include <stdint.h>

#define Bz  32
#define Sz  48
#define Vz  10000
#define CVz 9600
#define Hz  768
#define NHz 12
#define NLz 12
#define Gz  32
#define HDz 64
#define CPG (Hz/Gz)   // 24

// ------------------------- scratch (no allocation allowed) -------------------------
__device__ float g_h  [Bz*Sz*Hz];
__device__ float g_x  [Bz*Sz*Hz];
__device__ float g_qkv[Bz*Sz*3*Hz];
__device__ float g_a  [Bz*Sz*Hz];
__device__ float g_mlp[Bz*Sz*4*Hz];
__device__ float g_cat[Bz*(Sz-1)*2*Hz];
__device__ float g_a1 [Bz*(Sz-1)*2*Hz];

// ------------------------- tf32 helpers -------------------------
__device__ __forceinline__ uint32_t f2tf32(float x) {
    uint32_t r;
    asm("cvt.rna.tf32.f32 %0, %1;" : "=r"(r) : "f"(x));
    return r;
}

__device__ __forceinline__ void mma_tf32(float c[4],
                                         uint32_t a0, uint32_t a1, uint32_t a2, uint32_t a3,
                                         uint32_t b0, uint32_t b1) {
    asm volatile(
        "mma.sync.aligned.m16n8k8.row.col.f32.tf32.tf32.f32 "
        "{%0,%1,%2,%3},{%4,%5,%6,%7},{%8,%9},{%0,%1,%2,%3};"
        : "+f"(c[0]), "+f"(c[1]), "+f"(c[2]), "+f"(c[3])
        : "r"(a0), "r"(a1), "r"(a2), "r"(a3), "r"(b0), "r"(b1));
}

__device__ __forceinline__ float apply_act(float v, const float* __restrict__ bias,
                                           const float* __restrict__ res,
                                           int gr, int gc, int N, int mode) {
    if (mode & 1)  v += bias[gc];
    if (mode & 2)  v += res[(size_t)gr * N + gc];
    if (mode & 4) { float x = v;
        v = 0.5f*x*(1.f + tanhf(0.7978845608028654f*(x + 0.044715f*x*x*x))); }
    if (mode & 8)  v = fmaxf(v, 0.f);
    if (mode & 16) v = 1.f/(1.f + expf(-v));
    return v;
}

// ------------------------- sparse embedding + pos embed -------------------------
__global__ void embed_kernel(const float* __restrict__ visits,
                             const float* __restrict__ vemb,
                             const float* __restrict__ pemb,
                             float* __restrict__ out)
{
    int row = blockIdx.x;            // b*Sz + s
    int s   = row % Sz;
    const float* vrow = visits + (size_t)row * Vz;
    int t = threadIdx.x;             // 256 threads
    float acc[3];
#pragma unroll
    for (int i = 0; i < 3; i++) acc[i] = pemb[s*Hz + t + i*256];

    __shared__ int   s_idx[256];
    __shared__ float s_val[256];
    __shared__ int   wcnt[8];

    int lane = t & 31, w = t >> 5;

    for (int base = 0; base < Vz; base += 256) {
        __syncthreads();
        int v = base + t;
        float val = (v < Vz) ? vrow[v] : 0.f;
        unsigned m = __ballot_sync(0xffffffffu, val != 0.f);
        if (lane == 0) wcnt[w] = __popc(m);
        __syncthreads();
        int off = 0;
#pragma unroll
        for (int i = 0; i < 8; i++) { if (i < w) off += wcnt[i]; }
        int cnt = 0;
#pragma unroll
        for (int i = 0; i < 8; i++) cnt += wcnt[i];
        if (val != 0.f) {
            int p = off + __popc(m & ((1u << lane) - 1u));
            s_idx[p] = v; s_val[p] = val;
        }
        __syncthreads();
        for (int j = 0; j < cnt; j++) {
            const float* er = vemb + (size_t)s_idx[j] * Hz;
            float vv = s_val[j];
#pragma unroll
            for (int i = 0; i < 3; i++) acc[i] += vv * er[t + i*256];
        }
    }
    float* orow = out + (size_t)row * Hz;
#pragma unroll
    for (int i = 0; i < 3; i++) orow[t + i*256] = acc[i];
}

// ------------------------- group norm -------------------------
__global__ void groupnorm_kernel(const float* __restrict__ in, float* __restrict__ out,
                                 const float* __restrict__ w, const float* __restrict__ b)
{
    int bg = blockIdx.x;
    int bt = bg / Gz, g = bg % Gz;
    int t = threadIdx.x;             // 128 threads
    const int NELEM = Sz * CPG;      // 1152
    float sum = 0.f, sq = 0.f;
    for (int idx = t; idx < NELEM; idx += 128) {
        int s = idx / CPG, c = idx % CPG;
        float v = in[((size_t)bt*Sz + s)*Hz + g*CPG + c];
        sum += v; sq += v*v;
    }
    __shared__ float r1[128], r2[128];
    r1[t] = sum; r2[t] = sq; __syncthreads();
    for (int o = 64; o > 0; o >>= 1) {
        if (t < o) { r1[t] += r1[t+o]; r2[t] += r2[t+o]; }
        __syncthreads();
    }
    float mean = r1[0] / NELEM;
    float var  = r2[0] / NELEM - mean*mean;
    float inv  = rsqrtf(var + 1e-5f);
    for (int idx = t; idx < NELEM; idx += 128) {
        int s = idx / CPG, c = idx % CPG;
        int ch = g*CPG + c;
        size_t off = ((size_t)bt*Sz + s)*Hz + ch;
        out[off] = (in[off] - mean) * inv * w[ch] + b[ch];
    }
}

// ==================== tf32 tensor-core GEMM: C = act(A[M,K] @ W[K,N] + ...) ====================
// BM=128, BN=128, BK=32; 256 threads = 8 warps; warp tile 64x32 (2 M-warps x 4 N-warps)
// mode bits: 1=bias, 2=res-add, 4=gelu, 8=relu, 16=sigmoid
#define PADA 129
#define PADB 132

__global__ __launch_bounds__(256, 2)
void gemm_tf32_kernel(const float* __restrict__ A, const float* __restrict__ W,
                      const float* __restrict__ bias, const float* __restrict__ res,
                      float* __restrict__ C, int M, int N, int K, int mode)
{
    __shared__ uint32_t sA[32][PADA];   // [k][m]
    __shared__ uint32_t sB[32][PADB];   // [k][n]

    int t = threadIdx.x;
    int bm = blockIdx.y * 128;
    int bn = blockIdx.x * 128;
    int lane = t & 31, w = t >> 5;
    int wm = w & 1, wn = w >> 1;
    int m_base = wm * 64, n_base = wn * 32;
    int g = lane >> 2, tig = lane & 3;

    float acc[4][4][4];
#pragma unroll
    for (int i = 0; i < 4; i++)
#pragma unroll
        for (int j = 0; j < 4; j++)
#pragma unroll
            for (int q = 0; q < 4; q++) acc[i][j][q] = 0.f;

    for (int k0 = 0; k0 < K; k0 += 32) {
        // load A tile: 128m x 32k -> sA[k][m]
#pragma unroll
        for (int it = 0; it < 4; it++) {
            int idx = it * 256 + t;
            int mr = idx >> 3;            // 0..127
            int kq = (idx & 7) * 4;       // 0..28
            float4 a4 = make_float4(0.f, 0.f, 0.f, 0.f);
            if (bm + mr < M)
                a4 = *(const float4*)(A + (size_t)(bm + mr) * K + k0 + kq);
            sA[kq+0][mr] = f2tf32(a4.x);
            sA[kq+1][mr] = f2tf32(a4.y);
            sA[kq+2][mr] = f2tf32(a4.z);
            sA[kq+3][mr] = f2tf32(a4.w);
        }
        // load B tile: 32k x 128n -> sB[k][n]
#pragma unroll
        for (int it = 0; it < 4; it++) {
            int idx = it * 256 + t;
            int kr = idx >> 5;            // 0..31
            int nq = (idx & 31) * 4;      // 0..124
            float4 b4 = *(const float4*)(W + (size_t)(k0 + kr) * N + bn + nq);
            uint4 u;
            u.x = f2tf32(b4.x); u.y = f2tf32(b4.y);
            u.z = f2tf32(b4.z); u.w = f2tf32(b4.w);
            *(uint4*)&sB[kr][nq] = u;
        }
        __syncthreads();

#pragma unroll
        for (int ks = 0; ks < 4; ks++) {
            int kk = ks * 8;
            uint32_t af[4][4], bf[4][2];
#pragma unroll
            for (int mi = 0; mi < 4; mi++) {
                int m0 = m_base + mi * 16;
                af[mi][0] = sA[kk + tig    ][m0 + g];
                af[mi][1] = sA[kk + tig    ][m0 + g + 8];
                af[mi][2] = sA[kk + tig + 4][m0 + g];
                af[mi][3] = sA[kk + tig + 4][m0 + g + 8];
            }
#pragma unroll
            for (int ni = 0; ni < 4; ni++) {
                int n0 = n_base + ni * 8;
                bf[ni][0] = sB[kk + tig    ][n0 + g];
                bf[ni][1] = sB[kk + tig + 4][n0 + g];
            }
#pragma unroll
            for (int mi = 0; mi < 4; mi++)
#pragma unroll
                for (int ni = 0; ni < 4; ni++)
                    mma_tf32(acc[mi][ni], af[mi][0], af[mi][1], af[mi][2], af[mi][3],
                             bf[ni][0], bf[ni][1]);
        }
        __syncthreads();
    }

    // epilogue
#pragma unroll
    for (int mi = 0; mi < 4; mi++) {
        int gr0 = bm + m_base + mi * 16 + g;
        int gr1 = gr0 + 8;
#pragma unroll
        for (int ni = 0; ni < 4; ni++) {
            int gc = bn + n_base + ni * 8 + 2 * tig;
            if (gr0 < M) {
                float v0 = apply_act(acc[mi][ni][0], bias, res, gr0, gc,     N, mode);
                float v1 = apply_act(acc[mi][ni][1], bias, res, gr0, gc + 1, N, mode);
                *(float2*)(C + (size_t)gr0 * N + gc) = make_float2(v0, v1);
            }
            if (gr1 < M) {
                float v2 = apply_act(acc[mi][ni][2], bias, res, gr1, gc,     N, mode);
                float v3 = apply_act(acc[mi][ni][3], bias, res, gr1, gc + 1, N, mode);
                *(float2*)(C + (size_t)gr1 * N + gc) = make_float2(v2, v3);
            }
        }
    }
}

// ============ tf32 masked transposed GEMM: C = act(A[M,K] @ (tril(W[N,K]))^T + bias) ============
// W element [n,k] kept iff k <= n
__global__ __launch_bounds__(256, 2)
void gemm_t_tf32_kernel(const float* __restrict__ A, const float* __restrict__ Wr,
                        const float* __restrict__ bias,
                        float* __restrict__ C, int M, int N, int K, int mode)
{
    __shared__ uint32_t sA[32][PADA];   // [k][m]
    __shared__ uint32_t sB[32][PADB];   // [k][n]

    int t = threadIdx.x;
    int bm = blockIdx.y * 128;
    int bn = blockIdx.x * 128;
    int lane = t & 31, w = t >> 5;
    int wm = w & 1, wn = w >> 1;
    int m_base = wm * 64, n_base = wn * 32;
    int g = lane >> 2, tig = lane & 3;

    float acc[4][4][4];
#pragma unroll
    for (int i = 0; i < 4; i++)
#pragma unroll
        for (int j = 0; j < 4; j++)
#pragma unroll
            for (int q = 0; q < 4; q++) acc[i][j][q] = 0.f;

    for (int k0 = 0; k0 < K; k0 += 32) {
#pragma unroll
        for (int it = 0; it < 4; it++) {
            int idx = it * 256 + t;
            int mr = idx >> 3;
            int kq = (idx & 7) * 4;
            float4 a4 = make_float4(0.f, 0.f, 0.f, 0.f);
            if (bm + mr < M)
                a4 = *(const float4*)(A + (size_t)(bm + mr) * K + k0 + kq);
            sA[kq+0][mr] = f2tf32(a4.x);
            sA[kq+1][mr] = f2tf32(a4.y);
            sA[kq+2][mr] = f2tf32(a4.z);
            sA[kq+3][mr] = f2tf32(a4.w);
        }
        // B tile from W[N,K] rows: sB[k][n] = W[bn+n][k0+k] * (k0+k <= bn+n)
#pragma unroll
        for (int it = 0; it < 4; it++) {
            int idx = it * 256 + t;
            int n  = idx >> 3;            // 0..127
            int kq = (idx & 7) * 4;
            int gn = bn + n;
            float4 b4 = *(const float4*)(Wr + (size_t)gn * K + k0 + kq);
            int kg = k0 + kq;
            if (kg + 0 > gn) b4.x = 0.f;
            if (kg + 1 > gn) b4.y = 0.f;
            if (kg + 2 > gn) b4.z = 0.f;
            if (kg + 3 > gn) b4.w = 0.f;
            sB[kq+0][n] = f2tf32(b4.x);
            sB[kq+1][n] = f2tf32(b4.y);
            sB[kq+2][n] = f2tf32(b4.z);
            sB[kq+3][n] = f2tf32(b4.w);
        }
        __syncthreads();

#pragma unroll
        for (int ks = 0; ks < 4; ks++) {
            int kk = ks * 8;
            uint32_t af[4][4], bf[4][2];
#pragma unroll
            for (int mi = 0; mi < 4; mi++) {
                int m0 = m_base + mi * 16;
                af[mi][0] = sA[kk + tig    ][m0 + g];
                af[mi][1] = sA[kk + tig    ][m0 + g + 8];
                af[mi][2] = sA[kk + tig + 4][m0 + g];
                af[mi][3] = sA[kk + tig + 4][m0 + g + 8];
            }
#pragma unroll
            for (int ni = 0; ni < 4; ni++) {
                int n0 = n_base + ni * 8;
                bf[ni][0] = sB[kk + tig    ][n0 + g];
                bf[ni][1] = sB[kk + tig + 4][n0 + g];
            }
#pragma unroll
            for (int mi = 0; mi < 4; mi++)
#pragma unroll
                for (int ni = 0; ni < 4; ni++)
                    mma_tf32(acc[mi][ni], af[mi][0], af[mi][1], af[mi][2], af[mi][3],
                             bf[ni][0], bf[ni][1]);
        }
        __syncthreads();
    }

#pragma unroll
    for (int mi = 0; mi < 4; mi++) {
        int gr0 = bm + m_base + mi * 16 + g;
        int gr1 = gr0 + 8;
#pragma unroll
        for (int ni = 0; ni < 4; ni++) {
            int gc = bn + n_base + ni * 8 + 2 * tig;
            if (gr0 < M) {
                float v0 = apply_act(acc[mi][ni][0], bias, nullptr, gr0, gc,     N, mode);
                float v1 = apply_act(acc[mi][ni][1], bias, nullptr, gr0, gc + 1, N, mode);
                *(float2*)(C + (size_t)gr0 * N + gc) = make_float2(v0, v1);
            }
            if (gr1 < M) {
                float v2 = apply_act(acc[mi][ni][2], bias, nullptr, gr1, gc,     N, mode);
                float v3 = apply_act(acc[mi][ni][3], bias, nullptr, gr1, gc + 1, N, mode);
                *(float2*)(C + (size_t)gr1 * N + gc) = make_float2(v2, v3);
            }
        }
    }
}

// ------------------------- attention: one CTA per (batch, head) -------------------------
__global__ void attn_kernel(const float* __restrict__ qkv, float* __restrict__ out)
{
    int bh = blockIdx.x;
    int b = bh / NHz, hd = bh % NHz;
    __shared__ float sq[Sz][HDz], sk[Sz][HDz], sv[Sz][HDz];
    __shared__ float sc[Sz][Sz+1];
    int t = threadIdx.x;   // 128

    const float* base = qkv + (size_t)b * Sz * (3*Hz);
    for (int idx = t; idx < Sz*HDz; idx += 128) {
        int s = idx / HDz, d = idx % HDz;
        size_t o = (size_t)s * (3*Hz) + hd*HDz + d;
        sq[s][d] = base[o];
        sk[s][d] = base[o + Hz];
        sv[s][d] = base[o + 2*Hz];
    }
    __syncthreads();
    for (int idx = t; idx < Sz*Sz; idx += 128) {
        int i = idx / Sz, j = idx % Sz;
        float a = -1e10f;
        if (j <= i) {
            a = 0.f;
#pragma unroll
            for (int d = 0; d < HDz; d++) a += sq[i][d]*sk[j][d];
            a *= 0.125f;
        }
        sc[i][j] = a;
    }
    __syncthreads();
    if (t < Sz) {
        int i = t;
        float mx = -1e30f;
        for (int j = 0; j <= i; j++) mx = fmaxf(mx, sc[i][j]);
        float sum = 0.f;
        for (int j = 0; j < Sz; j++) { float e = expf(sc[i][j]-mx); sc[i][j] = e; sum += e; }
        float inv = 1.f/sum;
        for (int j = 0; j < Sz; j++) sc[i][j] *= inv;
    }
    __syncthreads();
    float* ob = out + (size_t)b * Sz * Hz + hd*HDz;
    for (int idx = t; idx < Sz*HDz; idx += 128) {
        int i = idx / HDz, d = idx % HDz;
        float a = 0.f;
#pragma unroll
        for (int j = 0; j < Sz; j++) a += sc[i][j]*sv[j][d];
        ob[(size_t)i*Hz + d] = a;
    }
}

// ------------------------- concat [h[:, :-1], h[:, 1:]] -------------------------
__global__ void concat_kernel(const float* __restrict__ x, float* __restrict__ cat)
{
    int idx = blockIdx.x * 256 + threadIdx.x;
    const int total = Bz*(Sz-1)*2*Hz;
    if (idx >= total) return;
    int c  = idx % (2*Hz);
    int bt = idx / (2*Hz);
    int tp = bt % (Sz-1), b = bt / (Sz-1);
    float v;
    if (c < Hz) v = x[((size_t)b*Sz + tp)*Hz + c];
    else        v = x[((size_t)b*Sz + tp + 1)*Hz + (c - Hz)];
    cat[idx] = v;
}

// ------------------------- launch -------------------------
extern "C" void kernel_launch(void* const* d_in, const int* in_sizes, int n_in,
                              void* d_out, int out_size)
{
    const float* visits = (const float*)d_in[0];
    const float* vemb   = (const float*)d_in[1];
    const float* pemb   = (const float*)d_in[2];
    const float* ln1w   = (const float*)d_in[3];
    const float* ln1b   = (const float*)d_in[4];
    const float* attnw  = (const float*)d_in[5];
    const float* attnb  = (const float*)d_in[6];
    const float* projw  = (const float*)d_in[7];
    const float* projb  = (const float*)d_in[8];
    const float* ln2w   = (const float*)d_in[9];
    const float* ln2b   = (const float*)d_in[10];
    const float* fcw    = (const float*)d_in[11];
    const float* fcb    = (const float*)d_in[12];
    const float* mprojw = (const float*)d_in[13];
    const float* mprojb = (const float*)d_in[14];
    const float* lnfw   = (const float*)d_in[15];
    const float* lnfb   = (const float*)d_in[16];
    const float* a1w    = (const float*)d_in[17];
    const float* a1b    = (const float*)d_in[18];
    const float* a2w    = (const float*)d_in[19];
    const float* a2b    = (const float*)d_in[20];
    float* out = (float*)d_out;

    float *ph, *px, *pqkv, *pa, *pmlp, *pcat, *pa1;
    cudaGetSymbolAddress((void**)&ph,   g_h);
    cudaGetSymbolAddress((void**)&px,   g_x);
    cudaGetSymbolAddress((void**)&pqkv, g_qkv);
    cudaGetSymbolAddress((void**)&pa,   g_a);
    cudaGetSymbolAddress((void**)&pmlp, g_mlp);
    cudaGetSymbolAddress((void**)&pcat, g_cat);
    cudaGetSymbolAddress((void**)&pa1,  g_a1);

    const int M = Bz * Sz;   // 1536

    embed_kernel<<<Bz*Sz, 256>>>(visits, vemb, pemb, ph);

    for (int l = 0; l < NLz; l++) {
        groupnorm_kernel<<<Bz*Gz, 128>>>(ph, px, ln1w + l*Hz, ln1b + l*Hz);
        gemm_tf32_kernel<<<dim3(3*Hz/128, M/128), 256>>>(
            px, attnw + (size_t)l*Hz*3*Hz, attnb + (size_t)l*3*Hz, nullptr,
            pqkv, M, 3*Hz, Hz, 1);
        attn_kernel<<<Bz*NHz, 128>>>(pqkv, pa);
        gemm_tf32_kernel<<<dim3(Hz/128, M/128), 256>>>(
            pa, projw + (size_t)l*Hz*Hz, projb + (size_t)l*Hz, ph,
            ph, M, Hz, Hz, 1|2);
        groupnorm_kernel<<<Bz*Gz, 128>>>(ph, px, ln2w + l*Hz, ln2b + l*Hz);
        gemm_tf32_kernel<<<dim3(4*Hz/128, M/128), 256>>>(
            px, fcw + (size_t)l*Hz*4*Hz, fcb + (size_t)l*4*Hz, nullptr,
            pmlp, M, 4*Hz, Hz, 1|4);
        gemm_tf32_kernel<<<dim3(Hz/128, M/128), 256>>>(
            pmlp, mprojw + (size_t)l*4*Hz*Hz, mprojb + (size_t)l*Hz, ph,
            ph, M, Hz, 4*Hz, 1|2);
    }

    groupnorm_kernel<<<Bz*Gz, 128>>>(ph, px, lnfw, lnfb);

    const int Mh = Bz * (Sz - 1);  // 1504
    concat_kernel<<<(Mh*2*Hz + 255)/256, 256>>>(px, pcat);
    gemm_t_tf32_kernel<<<dim3(2*Hz/128, (Mh + 127)/128), 256>>>(
        pcat, a1w, a1b, pa1, Mh, 2*Hz, 2*Hz, 1|8);
    gemm_t_tf32_kernel<<<dim3(CVz/128, (Mh + 127)/128), 256>>>(
        pa1, a2w, a2b, out, Mh, CVz, 2*Hz, 1|16);
}

// round 3
// speedup vs baseline: 3.1785x; 1.7010x over previous
#include <cuda_runtime.h>
#include <math.h>
#include <stdint.h>

#define Bz  32
#define Sz  48
#define Vz  10000
#define CVz 9600
#define Hz  768
#define NHz 12
#define NLz 12
#define Gz  32
#define HDz 64
#define CPG (Hz/Gz)   // 24

// ------------------------- scratch (no allocation allowed) -------------------------
__device__ float g_h  [Bz*Sz*Hz];
__device__ float g_x  [Bz*Sz*Hz];
__device__ float g_qkv[Bz*Sz*3*Hz];
__device__ float g_a  [Bz*Sz*Hz];
__device__ float g_mlp[Bz*Sz*4*Hz];
__device__ float g_cat[Bz*(Sz-1)*2*Hz];
__device__ float g_a1 [Bz*(Sz-1)*2*Hz];

// ------------------------- helpers -------------------------
__device__ __forceinline__ void mma_tf32(float c[4],
                                         uint32_t a0, uint32_t a1, uint32_t a2, uint32_t a3,
                                         uint32_t b0, uint32_t b1) {
    asm volatile(
        "mma.sync.aligned.m16n8k8.row.col.f32.tf32.tf32.f32 "
        "{%0,%1,%2,%3},{%4,%5,%6,%7},{%8,%9},{%0,%1,%2,%3};"
        : "+f"(c[0]), "+f"(c[1]), "+f"(c[2]), "+f"(c[3])
        : "r"(a0), "r"(a1), "r"(a2), "r"(a3), "r"(b0), "r"(b1));
}

__device__ __forceinline__ void cp_async16(void* smem, const void* gmem, bool pred) {
    uint32_t s = (uint32_t)__cvta_generic_to_shared(smem);
    int src_bytes = pred ? 16 : 0;   // 0 -> zero-fill
    asm volatile("cp.async.cg.shared.global [%0], [%1], 16, %2;\n"
                 :: "r"(s), "l"(gmem), "r"(src_bytes));
}
__device__ __forceinline__ void cp_commit() { asm volatile("cp.async.commit_group;\n"); }
__device__ __forceinline__ void cp_wait0()  { asm volatile("cp.async.wait_group 0;\n"); }

__device__ __forceinline__ float apply_act(float v, const float* __restrict__ bias,
                                           const float* __restrict__ res,
                                           int gr, int gc, int N, int mode) {
    if (mode & 1)  v += bias[gc];
    if (mode & 2)  v += res[(size_t)gr * N + gc];
    if (mode & 4) { float x = v;
        v = 0.5f*x*(1.f + tanhf(0.7978845608028654f*(x + 0.044715f*x*x*x))); }
    if (mode & 8)  v = fmaxf(v, 0.f);
    if (mode & 16) v = 1.f/(1.f + expf(-v));
    return v;
}

// ------------------------- sparse embedding + pos embed -------------------------
__global__ void embed_kernel(const float* __restrict__ visits,
                             const float* __restrict__ vemb,
                             const float* __restrict__ pemb,
                             float* __restrict__ out)
{
    int row = blockIdx.x;            // b*Sz + s
    int s   = row % Sz;
    const float* vrow = visits + (size_t)row * Vz;
    int t = threadIdx.x;             // 256 threads
    float acc[3];
#pragma unroll
    for (int i = 0; i < 3; i++) acc[i] = pemb[s*Hz + t + i*256];

    __shared__ int   s_idx[256];
    __shared__ float s_val[256];
    __shared__ int   wcnt[8];

    int lane = t & 31, w = t >> 5;

    for (int base = 0; base < Vz; base += 256) {
        __syncthreads();
        int v = base + t;
        float val = (v < Vz) ? vrow[v] : 0.f;
        unsigned m = __ballot_sync(0xffffffffu, val != 0.f);
        if (lane == 0) wcnt[w] = __popc(m);
        __syncthreads();
        int off = 0;
#pragma unroll
        for (int i = 0; i < 8; i++) { if (i < w) off += wcnt[i]; }
        int cnt = 0;
#pragma unroll
        for (int i = 0; i < 8; i++) cnt += wcnt[i];
        if (val != 0.f) {
            int p = off + __popc(m & ((1u << lane) - 1u));
            s_idx[p] = v; s_val[p] = val;
        }
        __syncthreads();
        for (int j = 0; j < cnt; j++) {
            const float* er = vemb + (size_t)s_idx[j] * Hz;
            float vv = s_val[j];
#pragma unroll
            for (int i = 0; i < 3; i++) acc[i] += vv * er[t + i*256];
        }
    }
    float* orow = out + (size_t)row * Hz;
#pragma unroll
    for (int i = 0; i < 3; i++) orow[t + i*256] = acc[i];
}

// ------------------------- group norm -------------------------
__global__ void groupnorm_kernel(const float* __restrict__ in, float* __restrict__ out,
                                 const float* __restrict__ w, const float* __restrict__ b)
{
    int bg = blockIdx.x;
    int bt = bg / Gz, g = bg % Gz;
    int t = threadIdx.x;             // 128 threads
    const int NELEM = Sz * CPG;      // 1152
    float sum = 0.f, sq = 0.f;
    for (int idx = t; idx < NELEM; idx += 128) {
        int s = idx / CPG, c = idx % CPG;
        float v = in[((size_t)bt*Sz + s)*Hz + g*CPG + c];
        sum += v; sq += v*v;
    }
    __shared__ float r1[128], r2[128];
    r1[t] = sum; r2[t] = sq; __syncthreads();
    for (int o = 64; o > 0; o >>= 1) {
        if (t < o) { r1[t] += r1[t+o]; r2[t] += r2[t+o]; }
        __syncthreads();
    }
    float mean = r1[0] / NELEM;
    float var  = r2[0] / NELEM - mean*mean;
    float inv  = rsqrtf(var + 1e-5f);
    for (int idx = t; idx < NELEM; idx += 128) {
        int s = idx / CPG, c = idx % CPG;
        int ch = g*CPG + c;
        size_t off = ((size_t)bt*Sz + s)*Hz + ch;
        out[off] = (in[off] - mean) * inv * w[ch] + b[ch];
    }
}

// ==================== pipelined tf32 GEMM: C = act(A[M,K] @ W[K,N] + ...) ====================
// BM template (64/128), BN=128, BK=16, cp.async double buffer, raw-fp32-as-tf32 (hw truncation).
// 256 threads = 8 warps laid out 2(m) x 4(n); warp tile (BM/2) x 32.
#define SAST 20    // sA row stride (words): bank = (20*g + tig) % 32 bijective
#define SBST 136   // sB row stride (words): bank = (8*tig + g) % 32 bijective

template<int BM>
__global__ __launch_bounds__(256, 2)
void gemm_tc_kernel(const float* __restrict__ A, const float* __restrict__ W,
                    const float* __restrict__ bias, const float* __restrict__ res,
                    float* __restrict__ C, int M, int N, int K, int mode)
{
    constexpr int MI = BM / 32;              // m16 frags per warp
    __shared__ float sA[2][BM][SAST];
    __shared__ float sB[2][16][SBST];

    int t = threadIdx.x;
    int bm = blockIdx.y * BM;
    int bn = blockIdx.x * 128;
    int lane = t & 31, w = t >> 5;
    int wm = w & 1, wn = w >> 1;
    int m_base = wm * (BM / 2), n_base = wn * 32;
    int g = lane >> 2, tig = lane & 3;

    float acc[MI][4][4];
#pragma unroll
    for (int i = 0; i < MI; i++)
#pragma unroll
        for (int j = 0; j < 4; j++)
#pragma unroll
            for (int q = 0; q < 4; q++) acc[i][j][q] = 0.f;

    const int KT = K / 16;

    // ---- tile loader ----
    auto load_tile = [&](int buf, int kt) {
        int k0 = kt * 16;
        // A: BM x 16 floats -> BM*4 float4, 256 thr -> BM/64 iters... (BM*4/256)
#pragma unroll
        for (int it = 0; it < BM / 64; it++) {
            int idx = it * 256 + t;
            int mr = idx >> 2;
            int kq = (idx & 3) * 4;
            cp_async16(&sA[buf][mr][kq], A + (size_t)(bm + mr) * K + k0 + kq, bm + mr < M);
        }
        // B: 16 x 128 floats -> 512 float4, 2 per thread
#pragma unroll
        for (int it = 0; it < 2; it++) {
            int idx = it * 256 + t;
            int kr = idx >> 5;
            int nq = (idx & 31) * 4;
            cp_async16(&sB[buf][kr][nq], W + (size_t)(k0 + kr) * N + bn + nq, true);
        }
        cp_commit();
    };

    load_tile(0, 0);
    cp_wait0();
    __syncthreads();

    int buf = 0;
    for (int kt = 0; kt < KT; kt++) {
        if (kt + 1 < KT) load_tile(buf ^ 1, kt + 1);

#pragma unroll
        for (int ks = 0; ks < 2; ks++) {
            int kk = ks * 8;
            uint32_t af[MI][4], bf[4][2];
#pragma unroll
            for (int mi = 0; mi < MI; mi++) {
                int m0 = m_base + mi * 16;
                af[mi][0] = __float_as_uint(sA[buf][m0 + g    ][kk + tig    ]);
                af[mi][1] = __float_as_uint(sA[buf][m0 + g + 8][kk + tig    ]);
                af[mi][2] = __float_as_uint(sA[buf][m0 + g    ][kk + tig + 4]);
                af[mi][3] = __float_as_uint(sA[buf][m0 + g + 8][kk + tig + 4]);
            }
#pragma unroll
            for (int ni = 0; ni < 4; ni++) {
                int n0 = n_base + ni * 8;
                bf[ni][0] = __float_as_uint(sB[buf][kk + tig    ][n0 + g]);
                bf[ni][1] = __float_as_uint(sB[buf][kk + tig + 4][n0 + g]);
            }
#pragma unroll
            for (int mi = 0; mi < MI; mi++)
#pragma unroll
                for (int ni = 0; ni < 4; ni++)
                    mma_tf32(acc[mi][ni], af[mi][0], af[mi][1], af[mi][2], af[mi][3],
                             bf[ni][0], bf[ni][1]);
        }
        if (kt + 1 < KT) cp_wait0();
        __syncthreads();
        buf ^= 1;
    }

    // epilogue
#pragma unroll
    for (int mi = 0; mi < MI; mi++) {
        int gr0 = bm + m_base + mi * 16 + g;
        int gr1 = gr0 + 8;
#pragma unroll
        for (int ni = 0; ni < 4; ni++) {
            int gc = bn + n_base + ni * 8 + 2 * tig;
            if (gr0 < M) {
                float v0 = apply_act(acc[mi][ni][0], bias, res, gr0, gc,     N, mode);
                float v1 = apply_act(acc[mi][ni][1], bias, res, gr0, gc + 1, N, mode);
                *(float2*)(C + (size_t)gr0 * N + gc) = make_float2(v0, v1);
            }
            if (gr1 < M) {
                float v2 = apply_act(acc[mi][ni][2], bias, res, gr1, gc,     N, mode);
                float v3 = apply_act(acc[mi][ni][3], bias, res, gr1, gc + 1, N, mode);
                *(float2*)(C + (size_t)gr1 * N + gc) = make_float2(v2, v3);
            }
        }
    }
}

// ======== pipelined masked-transposed GEMM: C = act(A[M,K] @ (tril(W[N,K]))^T + bias) ========
// W[n,k] kept iff k <= n. B stored [n][k] in smem (cp.async friendly), mask at fragment load.
__global__ __launch_bounds__(256, 2)
void gemm_t_tc_kernel(const float* __restrict__ A, const float* __restrict__ Wr,
                      const float* __restrict__ bias,
                      float* __restrict__ C, int M, int N, int K, int mode)
{
    constexpr int BM = 128, MI = 4;
    __shared__ float sA [2][BM][SAST];
    __shared__ float sBT[2][128][SAST];   // [n][k]

    int t = threadIdx.x;
    int bm = blockIdx.y * BM;
    int bn = blockIdx.x * 128;
    int lane = t & 31, w = t >> 5;
    int wm = w & 1, wn = w >> 1;
    int m_base = wm * 64, n_base = wn * 32;
    int g = lane >> 2, tig = lane & 3;

    float acc[MI][4][4];
#pragma unroll
    for (int i = 0; i < MI; i++)
#pragma unroll
        for (int j = 0; j < 4; j++)
#pragma unroll
            for (int q = 0; q < 4; q++) acc[i][j][q] = 0.f;

    const int KT = K / 16;

    auto load_tile = [&](int buf, int kt) {
        int k0 = kt * 16;
#pragma unroll
        for (int it = 0; it < 2; it++) {
            int idx = it * 256 + t;
            int mr = idx >> 2;
            int kq = (idx & 3) * 4;
            cp_async16(&sA[buf][mr][kq], A + (size_t)(bm + mr) * K + k0 + kq, bm + mr < M);
        }
#pragma unroll
        for (int it = 0; it < 2; it++) {
            int idx = it * 256 + t;
            int n  = idx >> 2;
            int kq = (idx & 3) * 4;
            cp_async16(&sBT[buf][n][kq], Wr + (size_t)(bn + n) * K + k0 + kq, true);
        }
        cp_commit();
    };

    load_tile(0, 0);
    cp_wait0();
    __syncthreads();

    int buf = 0;
    for (int kt = 0; kt < KT; kt++) {
        int k0 = kt * 16;
        if (kt + 1 < KT) load_tile(buf ^ 1, kt + 1);

#pragma unroll
        for (int ks = 0; ks < 2; ks++) {
            int kk = ks * 8;
            int kg0 = k0 + kk + tig;       // k of b0
            int kg1 = kg0 + 4;             // k of b1
            uint32_t af[MI][4], bf[4][2];
#pragma unroll
            for (int mi = 0; mi < MI; mi++) {
                int m0 = m_base + mi * 16;
                af[mi][0] = __float_as_uint(sA[buf][m0 + g    ][kk + tig    ]);
                af[mi][1] = __float_as_uint(sA[buf][m0 + g + 8][kk + tig    ]);
                af[mi][2] = __float_as_uint(sA[buf][m0 + g    ][kk + tig + 4]);
                af[mi][3] = __float_as_uint(sA[buf][m0 + g + 8][kk + tig + 4]);
            }
#pragma unroll
            for (int ni = 0; ni < 4; ni++) {
                int nl = n_base + ni * 8 + g;
                int gn = bn + nl;
                float b0 = sBT[buf][nl][kk + tig    ];
                float b1 = sBT[buf][nl][kk + tig + 4];
                bf[ni][0] = __float_as_uint(kg0 <= gn ? b0 : 0.f);
                bf[ni][1] = __float_as_uint(kg1 <= gn ? b1 : 0.f);
            }
#pragma unroll
            for (int mi = 0; mi < MI; mi++)
#pragma unroll
                for (int ni = 0; ni < 4; ni++)
                    mma_tf32(acc[mi][ni], af[mi][0], af[mi][1], af[mi][2], af[mi][3],
                             bf[ni][0], bf[ni][1]);
        }
        if (kt + 1 < KT) cp_wait0();
        __syncthreads();
        buf ^= 1;
    }

#pragma unroll
    for (int mi = 0; mi < MI; mi++) {
        int gr0 = bm + m_base + mi * 16 + g;
        int gr1 = gr0 + 8;
#pragma unroll
        for (int ni = 0; ni < 4; ni++) {
            int gc = bn + n_base + ni * 8 + 2 * tig;
            if (gr0 < M) {
                float v0 = apply_act(acc[mi][ni][0], bias, nullptr, gr0, gc,     N, mode);
                float v1 = apply_act(acc[mi][ni][1], bias, nullptr, gr0, gc + 1, N, mode);
                *(float2*)(C + (size_t)gr0 * N + gc) = make_float2(v0, v1);
            }
            if (gr1 < M) {
                float v2 = apply_act(acc[mi][ni][2], bias, nullptr, gr1, gc,     N, mode);
                float v3 = apply_act(acc[mi][ni][3], bias, nullptr, gr1, gc + 1, N, mode);
                *(float2*)(C + (size_t)gr1 * N + gc) = make_float2(v2, v3);
            }
        }
    }
}

// ------------------------- attention: warp-parallel softmax -------------------------
__global__ void attn_kernel(const float* __restrict__ qkv, float* __restrict__ out)
{
    int bh = blockIdx.x;
    int b = bh / NHz, hd = bh % NHz;
    __shared__ float sq[Sz][HDz+1], sk[Sz][HDz+1], sv[Sz][HDz+1];
    __shared__ float sp[4][Sz];
    int t = threadIdx.x;   // 128
    int lane = t & 31, wid = t >> 5;

    const float* base = qkv + (size_t)b * Sz * (3*Hz);
    for (int idx = t; idx < Sz*HDz; idx += 128) {
        int s = idx / HDz, d = idx % HDz;
        size_t o = (size_t)s * (3*Hz) + hd*HDz + d;
        sq[s][d] = base[o];
        sk[s][d] = base[o + Hz];
        sv[s][d] = base[o + 2*Hz];
    }
    __syncthreads();

    float* ob = out + (size_t)b * Sz * Hz + hd*HDz;

    for (int i = wid; i < Sz; i += 4) {
        int j1 = lane, j2 = lane + 32;
        float s1 = -1e30f, s2 = -1e30f;
        if (j1 <= i) {
            float a = 0.f;
#pragma unroll
            for (int d = 0; d < HDz; d++) a += sq[i][d] * sk[j1][d];
            s1 = a * 0.125f;
        }
        if (j2 <= i && j2 < Sz) {
            float a = 0.f;
#pragma unroll
            for (int d = 0; d < HDz; d++) a += sq[i][d] * sk[j2][d];
            s2 = a * 0.125f;
        }
        float mx = fmaxf(s1, s2);
#pragma unroll
        for (int o = 16; o > 0; o >>= 1) mx = fmaxf(mx, __shfl_xor_sync(0xffffffffu, mx, o));
        float e1 = (j1 <= i)            ? __expf(s1 - mx) : 0.f;
        float e2 = (j2 <= i && j2 < Sz) ? __expf(s2 - mx) : 0.f;
        float sum = e1 + e2;
#pragma unroll
        for (int o = 16; o > 0; o >>= 1) sum += __shfl_xor_sync(0xffffffffu, sum, o);
        float inv = 1.f / sum;
        sp[wid][j1] = e1 * inv;
        if (j2 < Sz) sp[wid][j2] = e2 * inv;
        __syncwarp();

        // out[i][d] for d = lane, lane+32
        float o1 = 0.f, o2 = 0.f;
        for (int j = 0; j <= i; j++) {
            float p = sp[wid][j];
            o1 += p * sv[j][lane];
            o2 += p * sv[j][lane + 32];
        }
        ob[(size_t)i*Hz + lane]      = o1;
        ob[(size_t)i*Hz + lane + 32] = o2;
    }
}

// ------------------------- concat [h[:, :-1], h[:, 1:]] -------------------------
__global__ void concat_kernel(const float* __restrict__ x, float* __restrict__ cat)
{
    int idx = blockIdx.x * 256 + threadIdx.x;
    const int total = Bz*(Sz-1)*2*Hz;
    if (idx >= total) return;
    int c  = idx % (2*Hz);
    int bt = idx / (2*Hz);
    int tp = bt % (Sz-1), b = bt / (Sz-1);
    float v;
    if (c < Hz) v = x[((size_t)b*Sz + tp)*Hz + c];
    else        v = x[((size_t)b*Sz + tp + 1)*Hz + (c - Hz)];
    cat[idx] = v;
}

// ------------------------- launch -------------------------
extern "C" void kernel_launch(void* const* d_in, const int* in_sizes, int n_in,
                              void* d_out, int out_size)
{
    const float* visits = (const float*)d_in[0];
    const float* vemb   = (const float*)d_in[1];
    const float* pemb   = (const float*)d_in[2];
    const float* ln1w   = (const float*)d_in[3];
    const float* ln1b   = (const float*)d_in[4];
    const float* attnw  = (const float*)d_in[5];
    const float* attnb  = (const float*)d_in[6];
    const float* projw  = (const float*)d_in[7];
    const float* projb  = (const float*)d_in[8];
    const float* ln2w   = (const float*)d_in[9];
    const float* ln2b   = (const float*)d_in[10];
    const float* fcw    = (const float*)d_in[11];
    const float* fcb    = (const float*)d_in[12];
    const float* mprojw = (const float*)d_in[13];
    const float* mprojb = (const float*)d_in[14];
    const float* lnfw   = (const float*)d_in[15];
    const float* lnfb   = (const float*)d_in[16];
    const float* a1w    = (const float*)d_in[17];
    const float* a1b    = (const float*)d_in[18];
    const float* a2w    = (const float*)d_in[19];
    const float* a2b    = (const float*)d_in[20];
    float* out = (float*)d_out;

    float *ph, *px, *pqkv, *pa, *pmlp, *pcat, *pa1;
    cudaGetSymbolAddress((void**)&ph,   g_h);
    cudaGetSymbolAddress((void**)&px,   g_x);
    cudaGetSymbolAddress((void**)&pqkv, g_qkv);
    cudaGetSymbolAddress((void**)&pa,   g_a);
    cudaGetSymbolAddress((void**)&pmlp, g_mlp);
    cudaGetSymbolAddress((void**)&pcat, g_cat);
    cudaGetSymbolAddress((void**)&pa1,  g_a1);

    const int M = Bz * Sz;   // 1536

    embed_kernel<<<Bz*Sz, 256>>>(visits, vemb, pemb, ph);

    for (int l = 0; l < NLz; l++) {
        groupnorm_kernel<<<Bz*Gz, 128>>>(ph, px, ln1w + l*Hz, ln1b + l*Hz);
        gemm_tc_kernel<128><<<dim3(3*Hz/128, M/128), 256>>>(
            px, attnw + (size_t)l*Hz*3*Hz, attnb + (size_t)l*3*Hz, nullptr,
            pqkv, M, 3*Hz, Hz, 1);
        attn_kernel<<<Bz*NHz, 128>>>(pqkv, pa);
        gemm_tc_kernel<64><<<dim3(Hz/128, M/64), 256>>>(
            pa, projw + (size_t)l*Hz*Hz, projb + (size_t)l*Hz, ph,
            ph, M, Hz, Hz, 1|2);
        groupnorm_kernel<<<Bz*Gz, 128>>>(ph, px, ln2w + l*Hz, ln2b + l*Hz);
        gemm_tc_kernel<128><<<dim3(4*Hz/128, M/128), 256>>>(
            px, fcw + (size_t)l*Hz*4*Hz, fcb + (size_t)l*4*Hz, nullptr,
            pmlp, M, 4*Hz, Hz, 1|4);
        gemm_tc_kernel<64><<<dim3(Hz/128, M/64), 256>>>(
            pmlp, mprojw + (size_t)l*4*Hz*Hz, mprojb + (size_t)l*Hz, ph,
            ph, M, Hz, 4*Hz, 1|2);
    }

    groupnorm_kernel<<<Bz*Gz, 128>>>(ph, px, lnfw, lnfb);

    const int Mh = Bz * (Sz - 1);  // 1504
    concat_kernel<<<(Mh*2*Hz + 255)/256, 256>>>(px, pcat);
    gemm_t_tc_kernel<<<dim3(2*Hz/128, (Mh + 127)/128), 256>>>(
        pcat, a1w, a1b, pa1, Mh, 2*Hz, 2*Hz, 1|8);
    gemm_t_tc_kernel<<<dim3(CVz/128, (Mh + 127)/128), 256>>>(
        pa1, a2w, a2b, out, Mh, CVz, 2*Hz, 1|16);
}

// round 4
// speedup vs baseline: 3.8315x; 1.2054x over previous
#include <cuda_runtime.h>
#include <math.h>
#include <stdint.h>

#define Bz  32
#define Sz  48
#define Vz  10000
#define CVz 9600
#define Hz  768
#define NHz 12
#define NLz 12
#define Gz  32
#define HDz 64
#define CPG (Hz/Gz)   // 24

// ------------------------- scratch (no allocation allowed) -------------------------
__device__ float g_h  [Bz*Sz*Hz];
__device__ float g_x  [Bz*Sz*Hz];
__device__ float g_qkv[Bz*Sz*3*Hz];
__device__ float g_a  [Bz*Sz*Hz];
__device__ float g_mlp[Bz*Sz*4*Hz];
__device__ float g_cat[Bz*(Sz-1)*2*Hz];
__device__ float g_a1 [Bz*(Sz-1)*2*Hz];

// ------------------------- helpers -------------------------
__device__ __forceinline__ void mma_tf32(float c[4],
                                         uint32_t a0, uint32_t a1, uint32_t a2, uint32_t a3,
                                         uint32_t b0, uint32_t b1) {
    asm volatile(
        "mma.sync.aligned.m16n8k8.row.col.f32.tf32.tf32.f32 "
        "{%0,%1,%2,%3},{%4,%5,%6,%7},{%8,%9},{%0,%1,%2,%3};"
        : "+f"(c[0]), "+f"(c[1]), "+f"(c[2]), "+f"(c[3])
        : "r"(a0), "r"(a1), "r"(a2), "r"(a3), "r"(b0), "r"(b1));
}

__device__ __forceinline__ void cp_async16(void* smem, const void* gmem, bool pred) {
    uint32_t s = (uint32_t)__cvta_generic_to_shared(smem);
    int src_bytes = pred ? 16 : 0;   // 0 -> zero-fill
    asm volatile("cp.async.cg.shared.global [%0], [%1], 16, %2;\n"
                 :: "r"(s), "l"(gmem), "r"(src_bytes));
}
__device__ __forceinline__ void cp_commit() { asm volatile("cp.async.commit_group;\n"); }
__device__ __forceinline__ void cp_wait2()  { asm volatile("cp.async.wait_group 2;\n"); }

__device__ __forceinline__ float apply_act(float v, const float* __restrict__ bias,
                                           const float* __restrict__ res,
                                           int gr, int gc, int N, int mode) {
    if (mode & 1)  v += bias[gc];
    if (mode & 2)  v += res[(size_t)gr * N + gc];
    if (mode & 4) {                       // gelu(tanh approx) via expf identity
        float x = v;
        float y = 0.7978845608028654f * (x + 0.044715f * x * x * x);
        y = fminf(fmaxf(y, -15.f), 15.f);
        float e = __expf(2.f * y);
        float th = (e - 1.f) / (e + 1.f);
        v = 0.5f * x * (1.f + th);
    }
    if (mode & 8)  v = fmaxf(v, 0.f);
    if (mode & 16) v = 1.f / (1.f + __expf(-v));
    return v;
}

// ------------------------- sparse embedding + pos embed -------------------------
__global__ void embed_kernel(const float* __restrict__ visits,
                             const float* __restrict__ vemb,
                             const float* __restrict__ pemb,
                             float* __restrict__ out)
{
    int row = blockIdx.x;            // b*Sz + s
    int s   = row % Sz;
    const float* vrow = visits + (size_t)row * Vz;
    int t = threadIdx.x;             // 256 threads
    float acc[3];
#pragma unroll
    for (int i = 0; i < 3; i++) acc[i] = pemb[s*Hz + t + i*256];

    __shared__ int   s_idx[256];
    __shared__ float s_val[256];
    __shared__ int   wcnt[8];

    int lane = t & 31, w = t >> 5;

    for (int base = 0; base < Vz; base += 256) {
        __syncthreads();
        int v = base + t;
        float val = (v < Vz) ? vrow[v] : 0.f;
        unsigned m = __ballot_sync(0xffffffffu, val != 0.f);
        if (lane == 0) wcnt[w] = __popc(m);
        __syncthreads();
        int off = 0;
#pragma unroll
        for (int i = 0; i < 8; i++) { if (i < w) off += wcnt[i]; }
        int cnt = 0;
#pragma unroll
        for (int i = 0; i < 8; i++) cnt += wcnt[i];
        if (val != 0.f) {
            int p = off + __popc(m & ((1u << lane) - 1u));
            s_idx[p] = v; s_val[p] = val;
        }
        __syncthreads();
        for (int j = 0; j < cnt; j++) {
            const float* er = vemb + (size_t)s_idx[j] * Hz;
            float vv = s_val[j];
#pragma unroll
            for (int i = 0; i < 3; i++) acc[i] += vv * er[t + i*256];
        }
    }
    float* orow = out + (size_t)row * Hz;
#pragma unroll
    for (int i = 0; i < 3; i++) orow[t + i*256] = acc[i];
}

// ------------------------- group norm -------------------------
__global__ void groupnorm_kernel(const float* __restrict__ in, float* __restrict__ out,
                                 const float* __restrict__ w, const float* __restrict__ b)
{
    int bg = blockIdx.x;
    int bt = bg / Gz, g = bg % Gz;
    int t = threadIdx.x;             // 128 threads
    const int NELEM = Sz * CPG;      // 1152
    float sum = 0.f, sq = 0.f;
    for (int idx = t; idx < NELEM; idx += 128) {
        int s = idx / CPG, c = idx % CPG;
        float v = in[((size_t)bt*Sz + s)*Hz + g*CPG + c];
        sum += v; sq += v*v;
    }
    __shared__ float r1[128], r2[128];
    r1[t] = sum; r2[t] = sq; __syncthreads();
    for (int o = 64; o > 0; o >>= 1) {
        if (t < o) { r1[t] += r1[t+o]; r2[t] += r2[t+o]; }
        __syncthreads();
    }
    float mean = r1[0] / NELEM;
    float var  = r2[0] / NELEM - mean*mean;
    float inv  = rsqrtf(var + 1e-5f);
    for (int idx = t; idx < NELEM; idx += 128) {
        int s = idx / CPG, c = idx % CPG;
        int ch = g*CPG + c;
        size_t off = ((size_t)bt*Sz + s)*Hz + ch;
        out[off] = (in[off] - mean) * inv * w[ch] + b[ch];
    }
}

// ==================== 4-stage pipelined tf32 GEMM: C = act(A[M,K] @ W[K,N] + ...) ====================
// BM template (64/128), BN=128, BK=16, cp.async 4-stage ring, raw-fp32-as-tf32 (hw truncation).
// 256 threads = 8 warps laid out 2(m) x 4(n); warp tile (BM/2) x 32. Dynamic smem.
#define SAST 20    // sA row stride (words): bank = (20*g + tig) % 32 bijective
#define SBST 136   // sB row stride (words): bank = (8*tig + g) % 32 bijective
#define STG  4

template<int BM>
__global__ __launch_bounds__(256, 2)
void gemm_tc_kernel(const float* __restrict__ A, const float* __restrict__ W,
                    const float* __restrict__ bias, const float* __restrict__ res,
                    float* __restrict__ C, int M, int N, int K, int mode)
{
    constexpr int MI = BM / 32;
    constexpr int A_ELE = BM * SAST;
    constexpr int B_ELE = 16 * SBST;
    extern __shared__ float smem[];
    float* sAb = smem;                 // [STG][BM][SAST]
    float* sBb = smem + STG * A_ELE;   // [STG][16][SBST]

    int t = threadIdx.x;
    int bm = blockIdx.y * BM;
    int bn = blockIdx.x * 128;
    int lane = t & 31, w = t >> 5;
    int wm = w & 1, wn = w >> 1;
    int m_base = wm * (BM / 2), n_base = wn * 32;
    int g = lane >> 2, tig = lane & 3;

    float acc[MI][4][4];
#pragma unroll
    for (int i = 0; i < MI; i++)
#pragma unroll
        for (int j = 0; j < 4; j++)
#pragma unroll
            for (int q = 0; q < 4; q++) acc[i][j][q] = 0.f;

    const int KT = K / 16;

    auto load_tile = [&](int st, int kt) {
        int k0 = kt * 16;
        float* sA = sAb + st * A_ELE;
        float* sB = sBb + st * B_ELE;
#pragma unroll
        for (int it = 0; it < BM / 64; it++) {
            int idx = it * 256 + t;
            int mr = idx >> 2;
            int kq = (idx & 3) * 4;
            cp_async16(sA + mr * SAST + kq, A + (size_t)(bm + mr) * K + k0 + kq, bm + mr < M);
        }
#pragma unroll
        for (int it = 0; it < 2; it++) {
            int idx = it * 256 + t;
            int kr = idx >> 5;
            int nq = (idx & 31) * 4;
            cp_async16(sB + kr * SBST + nq, W + (size_t)(k0 + kr) * N + bn + nq, true);
        }
    };

    // prefetch 3 stages
#pragma unroll
    for (int s = 0; s < 3; s++) { load_tile(s, s); cp_commit(); }

    for (int kt = 0; kt < KT; kt++) {
        cp_wait2();            // tile kt ready (constant 1-commit-per-iter scheme)
        __syncthreads();
        if (kt + 3 < KT) load_tile((kt + 3) & 3, kt + 3);
        cp_commit();

        const float* sA = sAb + (kt & 3) * A_ELE;
        const float* sB = sBb + (kt & 3) * B_ELE;
#pragma unroll
        for (int ks = 0; ks < 2; ks++) {
            int kk = ks * 8;
            uint32_t af[MI][4], bf[4][2];
#pragma unroll
            for (int mi = 0; mi < MI; mi++) {
                int m0 = m_base + mi * 16;
                af[mi][0] = __float_as_uint(sA[(m0 + g    ) * SAST + kk + tig    ]);
                af[mi][1] = __float_as_uint(sA[(m0 + g + 8) * SAST + kk + tig    ]);
                af[mi][2] = __float_as_uint(sA[(m0 + g    ) * SAST + kk + tig + 4]);
                af[mi][3] = __float_as_uint(sA[(m0 + g + 8) * SAST + kk + tig + 4]);
            }
#pragma unroll
            for (int ni = 0; ni < 4; ni++) {
                int n0 = n_base + ni * 8;
                bf[ni][0] = __float_as_uint(sB[(kk + tig    ) * SBST + n0 + g]);
                bf[ni][1] = __float_as_uint(sB[(kk + tig + 4) * SBST + n0 + g]);
            }
#pragma unroll
            for (int mi = 0; mi < MI; mi++)
#pragma unroll
                for (int ni = 0; ni < 4; ni++)
                    mma_tf32(acc[mi][ni], af[mi][0], af[mi][1], af[mi][2], af[mi][3],
                             bf[ni][0], bf[ni][1]);
        }
        __syncthreads();
    }

    // epilogue
#pragma unroll
    for (int mi = 0; mi < MI; mi++) {
        int gr0 = bm + m_base + mi * 16 + g;
        int gr1 = gr0 + 8;
#pragma unroll
        for (int ni = 0; ni < 4; ni++) {
            int gc = bn + n_base + ni * 8 + 2 * tig;
            if (gr0 < M) {
                float v0 = apply_act(acc[mi][ni][0], bias, res, gr0, gc,     N, mode);
                float v1 = apply_act(acc[mi][ni][1], bias, res, gr0, gc + 1, N, mode);
                *(float2*)(C + (size_t)gr0 * N + gc) = make_float2(v0, v1);
            }
            if (gr1 < M) {
                float v2 = apply_act(acc[mi][ni][2], bias, res, gr1, gc,     N, mode);
                float v3 = apply_act(acc[mi][ni][3], bias, res, gr1, gc + 1, N, mode);
                *(float2*)(C + (size_t)gr1 * N + gc) = make_float2(v2, v3);
            }
        }
    }
}

// ======== 4-stage masked-transposed GEMM: C = act(A[M,K] @ (tril(W[N,K]))^T + bias) ========
// W[n,k] kept iff k <= n. B stored [n][k] in smem; mask applied at fragment load,
// skipped entirely (uniform branch) for CTAs whose n-range makes tril trivially full.
__global__ __launch_bounds__(256, 2)
void gemm_t_tc_kernel(const float* __restrict__ A, const float* __restrict__ Wr,
                      const float* __restrict__ bias,
                      float* __restrict__ C, int M, int N, int K, int mode)
{
    constexpr int BM = 128, MI = 4;
    constexpr int A_ELE = 128 * SAST;
    extern __shared__ float smem[];
    float* sAb  = smem;                 // [STG][128][SAST]
    float* sBTb = smem + STG * A_ELE;   // [STG][128][SAST]  ([n][k])

    int t = threadIdx.x;
    int bm = blockIdx.y * BM;
    int bn = blockIdx.x * 128;
    int lane = t & 31, w = t >> 5;
    int wm = w & 1, wn = w >> 1;
    int m_base = wm * 64, n_base = wn * 32;
    int g = lane >> 2, tig = lane & 3;
    const bool need_mask = (bn < K);    // uniform over CTA

    float acc[MI][4][4];
#pragma unroll
    for (int i = 0; i < MI; i++)
#pragma unroll
        for (int j = 0; j < 4; j++)
#pragma unroll
            for (int q = 0; q < 4; q++) acc[i][j][q] = 0.f;

    const int KT = K / 16;

    auto load_tile = [&](int st, int kt) {
        int k0 = kt * 16;
        float* sA  = sAb  + st * A_ELE;
        float* sBT = sBTb + st * A_ELE;
#pragma unroll
        for (int it = 0; it < 2; it++) {
            int idx = it * 256 + t;
            int mr = idx >> 2;
            int kq = (idx & 3) * 4;
            cp_async16(sA + mr * SAST + kq, A + (size_t)(bm + mr) * K + k0 + kq, bm + mr < M);
        }
#pragma unroll
        for (int it = 0; it < 2; it++) {
            int idx = it * 256 + t;
            int n  = idx >> 2;
            int kq = (idx & 3) * 4;
            cp_async16(sBT + n * SAST + kq, Wr + (size_t)(bn + n) * K + k0 + kq, true);
        }
    };

#pragma unroll
    for (int s = 0; s < 3; s++) { load_tile(s, s); cp_commit(); }

    for (int kt = 0; kt < KT; kt++) {
        cp_wait2();
        __syncthreads();
        if (kt + 3 < KT) load_tile((kt + 3) & 3, kt + 3);
        cp_commit();

        int k0 = kt * 16;
        const float* sA  = sAb  + (kt & 3) * A_ELE;
        const float* sBT = sBTb + (kt & 3) * A_ELE;
#pragma unroll
        for (int ks = 0; ks < 2; ks++) {
            int kk = ks * 8;
            uint32_t af[MI][4], bf[4][2];
#pragma unroll
            for (int mi = 0; mi < MI; mi++) {
                int m0 = m_base + mi * 16;
                af[mi][0] = __float_as_uint(sA[(m0 + g    ) * SAST + kk + tig    ]);
                af[mi][1] = __float_as_uint(sA[(m0 + g + 8) * SAST + kk + tig    ]);
                af[mi][2] = __float_as_uint(sA[(m0 + g    ) * SAST + kk + tig + 4]);
                af[mi][3] = __float_as_uint(sA[(m0 + g + 8) * SAST + kk + tig + 4]);
            }
            if (need_mask) {
                int kg0 = k0 + kk + tig;
                int kg1 = kg0 + 4;
#pragma unroll
                for (int ni = 0; ni < 4; ni++) {
                    int nl = n_base + ni * 8 + g;
                    int gn = bn + nl;
                    float b0 = sBT[nl * SAST + kk + tig    ];
                    float b1 = sBT[nl * SAST + kk + tig + 4];
                    bf[ni][0] = __float_as_uint(kg0 <= gn ? b0 : 0.f);
                    bf[ni][1] = __float_as_uint(kg1 <= gn ? b1 : 0.f);
                }
            } else {
#pragma unroll
                for (int ni = 0; ni < 4; ni++) {
                    int nl = n_base + ni * 8 + g;
                    bf[ni][0] = __float_as_uint(sBT[nl * SAST + kk + tig    ]);
                    bf[ni][1] = __float_as_uint(sBT[nl * SAST + kk + tig + 4]);
                }
            }
#pragma unroll
            for (int mi = 0; mi < MI; mi++)
#pragma unroll
                for (int ni = 0; ni < 4; ni++)
                    mma_tf32(acc[mi][ni], af[mi][0], af[mi][1], af[mi][2], af[mi][3],
                             bf[ni][0], bf[ni][1]);
        }
        __syncthreads();
    }

#pragma unroll
    for (int mi = 0; mi < MI; mi++) {
        int gr0 = bm + m_base + mi * 16 + g;
        int gr1 = gr0 + 8;
#pragma unroll
        for (int ni = 0; ni < 4; ni++) {
            int gc = bn + n_base + ni * 8 + 2 * tig;
            if (gr0 < M) {
                float v0 = apply_act(acc[mi][ni][0], bias, nullptr, gr0, gc,     N, mode);
                float v1 = apply_act(acc[mi][ni][1], bias, nullptr, gr0, gc + 1, N, mode);
                *(float2*)(C + (size_t)gr0 * N + gc) = make_float2(v0, v1);
            }
            if (gr1 < M) {
                float v2 = apply_act(acc[mi][ni][2], bias, nullptr, gr1, gc,     N, mode);
                float v3 = apply_act(acc[mi][ni][3], bias, nullptr, gr1, gc + 1, N, mode);
                *(float2*)(C + (size_t)gr1 * N + gc) = make_float2(v2, v3);
            }
        }
    }
}

// ------------------------- attention: warp-parallel softmax, 8 warps/CTA -------------------------
__global__ void attn_kernel(const float* __restrict__ qkv, float* __restrict__ out)
{
    int bh = blockIdx.x;
    int b = bh / NHz, hd = bh % NHz;
    __shared__ float sq[Sz][HDz+1], sk[Sz][HDz+1], sv[Sz][HDz+1];
    __shared__ float sp[8][Sz];
    int t = threadIdx.x;   // 256
    int lane = t & 31, wid = t >> 5;

    const float* base = qkv + (size_t)b * Sz * (3*Hz);
    for (int idx = t; idx < Sz*HDz; idx += 256) {
        int s = idx / HDz, d = idx % HDz;
        size_t o = (size_t)s * (3*Hz) + hd*HDz + d;
        sq[s][d] = base[o];
        sk[s][d] = base[o + Hz];
        sv[s][d] = base[o + 2*Hz];
    }
    __syncthreads();

    float* ob = out + (size_t)b * Sz * Hz + hd*HDz;

    for (int i = wid; i < Sz; i += 8) {
        int j1 = lane, j2 = lane + 32;
        float s1 = -1e30f, s2 = -1e30f;
        if (j1 <= i) {
            float a = 0.f;
#pragma unroll
            for (int d = 0; d < HDz; d++) a += sq[i][d] * sk[j1][d];
            s1 = a * 0.125f;
        }
        if (j2 <= i && j2 < Sz) {
            float a = 0.f;
#pragma unroll
            for (int d = 0; d < HDz; d++) a += sq[i][d] * sk[j2][d];
            s2 = a * 0.125f;
        }
        float mx = fmaxf(s1, s2);
#pragma unroll
        for (int o = 16; o > 0; o >>= 1) mx = fmaxf(mx, __shfl_xor_sync(0xffffffffu, mx, o));
        float e1 = (j1 <= i)            ? __expf(s1 - mx) : 0.f;
        float e2 = (j2 <= i && j2 < Sz) ? __expf(s2 - mx) : 0.f;
        float sum = e1 + e2;
#pragma unroll
        for (int o = 16; o > 0; o >>= 1) sum += __shfl_xor_sync(0xffffffffu, sum, o);
        float inv = 1.f / sum;
        sp[wid][j1] = e1 * inv;
        if (j2 < Sz) sp[wid][j2] = e2 * inv;
        __syncwarp();

        float o1 = 0.f, o2 = 0.f;
        for (int j = 0; j <= i; j++) {
            float p = sp[wid][j];
            o1 += p * sv[j][lane];
            o2 += p * sv[j][lane + 32];
        }
        ob[(size_t)i*Hz + lane]      = o1;
        ob[(size_t)i*Hz + lane + 32] = o2;
    }
}

// ------------------------- concat [h[:, :-1], h[:, 1:]] -------------------------
__global__ void concat_kernel(const float* __restrict__ x, float* __restrict__ cat)
{
    int idx = blockIdx.x * 256 + threadIdx.x;
    const int total = Bz*(Sz-1)*2*Hz;
    if (idx >= total) return;
    int c  = idx % (2*Hz);
    int bt = idx / (2*Hz);
    int tp = bt % (Sz-1), b = bt / (Sz-1);
    float v;
    if (c < Hz) v = x[((size_t)b*Sz + tp)*Hz + c];
    else        v = x[((size_t)b*Sz + tp + 1)*Hz + (c - Hz)];
    cat[idx] = v;
}

// ------------------------- launch -------------------------
extern "C" void kernel_launch(void* const* d_in, const int* in_sizes, int n_in,
                              void* d_out, int out_size)
{
    const float* visits = (const float*)d_in[0];
    const float* vemb   = (const float*)d_in[1];
    const float* pemb   = (const float*)d_in[2];
    const float* ln1w   = (const float*)d_in[3];
    const float* ln1b   = (const float*)d_in[4];
    const float* attnw  = (const float*)d_in[5];
    const float* attnb  = (const float*)d_in[6];
    const float* projw  = (const float*)d_in[7];
    const float* projb  = (const float*)d_in[8];
    const float* ln2w   = (const float*)d_in[9];
    const float* ln2b   = (const float*)d_in[10];
    const float* fcw    = (const float*)d_in[11];
    const float* fcb    = (const float*)d_in[12];
    const float* mprojw = (const float*)d_in[13];
    const float* mprojb = (const float*)d_in[14];
    const float* lnfw   = (const float*)d_in[15];
    const float* lnfb   = (const float*)d_in[16];
    const float* a1w    = (const float*)d_in[17];
    const float* a1b    = (const float*)d_in[18];
    const float* a2w    = (const float*)d_in[19];
    const float* a2b    = (const float*)d_in[20];
    float* out = (float*)d_out;

    float *ph, *px, *pqkv, *pa, *pmlp, *pcat, *pa1;
    cudaGetSymbolAddress((void**)&ph,   g_h);
    cudaGetSymbolAddress((void**)&px,   g_x);
    cudaGetSymbolAddress((void**)&pqkv, g_qkv);
    cudaGetSymbolAddress((void**)&pa,   g_a);
    cudaGetSymbolAddress((void**)&pmlp, g_mlp);
    cudaGetSymbolAddress((void**)&pcat, g_cat);
    cudaGetSymbolAddress((void**)&pa1,  g_a1);

    // dynamic smem sizes (4-stage)
    const int SM128 = STG * (128*SAST + 16*SBST) * 4;   // 75776 B
    const int SM64  = STG * ( 64*SAST + 16*SBST) * 4;   // 55296 B
    const int SMT   = STG * (128*SAST * 2) * 4;         // 81920 B
    cudaFuncSetAttribute(gemm_tc_kernel<128>, cudaFuncAttributeMaxDynamicSharedMemorySize, SM128);
    cudaFuncSetAttribute(gemm_tc_kernel<64>,  cudaFuncAttributeMaxDynamicSharedMemorySize, SM64);
    cudaFuncSetAttribute(gemm_t_tc_kernel,    cudaFuncAttributeMaxDynamicSharedMemorySize, SMT);

    const int M = Bz * Sz;   // 1536

    embed_kernel<<<Bz*Sz, 256>>>(visits, vemb, pemb, ph);

    for (int l = 0; l < NLz; l++) {
        groupnorm_kernel<<<Bz*Gz, 128>>>(ph, px, ln1w + l*Hz, ln1b + l*Hz);
        gemm_tc_kernel<128><<<dim3(3*Hz/128, M/128), 256, SM128>>>(
            px, attnw + (size_t)l*Hz*3*Hz, attnb + (size_t)l*3*Hz, nullptr,
            pqkv, M, 3*Hz, Hz, 1);
        attn_kernel<<<Bz*NHz, 256>>>(pqkv, pa);
        gemm_tc_kernel<64><<<dim3(Hz/128, M/64), 256, SM64>>>(
            pa, projw + (size_t)l*Hz*Hz, projb + (size_t)l*Hz, ph,
            ph, M, Hz, Hz, 1|2);
        groupnorm_kernel<<<Bz*Gz, 128>>>(ph, px, ln2w + l*Hz, ln2b + l*Hz);
        gemm_tc_kernel<128><<<dim3(4*Hz/128, M/128), 256, SM128>>>(
            px, fcw + (size_t)l*Hz*4*Hz, fcb + (size_t)l*4*Hz, nullptr,
            pmlp, M, 4*Hz, Hz, 1|4);
        gemm_tc_kernel<64><<<dim3(Hz/128, M/64), 256, SM64>>>(
            pmlp, mprojw + (size_t)l*4*Hz*Hz, mprojb + (size_t)l*Hz, ph,
            ph, M, Hz, 4*Hz, 1|2);
    }

    groupnorm_kernel<<<Bz*Gz, 128>>>(ph, px, lnfw, lnfb);

    const int Mh = Bz * (Sz - 1);  // 1504
    concat_kernel<<<(Mh*2*Hz + 255)/256, 256>>>(px, pcat);
    gemm_t_tc_kernel<<<dim3(2*Hz/128, (Mh + 127)/128), 256, SMT>>>(
        pcat, a1w, a1b, pa1, Mh, 2*Hz, 2*Hz, 1|8);
    gemm_t_tc_kernel<<<dim3(CVz/128, (Mh + 127)/128), 256, SMT>>>(
        pa1, a2w, a2b, out, Mh, CVz, 2*Hz, 1|16);
}

// round 5
// speedup vs baseline: 3.9050x; 1.0192x over previous
#include <cuda_runtime.h>
#include <math.h>
#include <stdint.h>

#define Bz  32
#define Sz  48
#define Vz  10000
#define CVz 9600
#define Hz  768
#define NHz 12
#define NLz 12
#define Gz  32
#define HDz 64
#define CPG (Hz/Gz)   // 24

// ------------------------- scratch (no allocation allowed) -------------------------
__device__ float g_h  [Bz*Sz*Hz];
__device__ float g_x  [Bz*Sz*Hz];
__device__ float g_qkv[Bz*Sz*3*Hz];
__device__ float g_a  [Bz*Sz*Hz];
__device__ float g_mlp[Bz*Sz*4*Hz];
__device__ float g_cat[Bz*(Sz-1)*2*Hz];
__device__ float g_a1 [Bz*(Sz-1)*2*Hz];

// ------------------------- helpers -------------------------
__device__ __forceinline__ void mma_tf32(float c[4],
                                         uint32_t a0, uint32_t a1, uint32_t a2, uint32_t a3,
                                         uint32_t b0, uint32_t b1) {
    asm volatile(
        "mma.sync.aligned.m16n8k8.row.col.f32.tf32.tf32.f32 "
        "{%0,%1,%2,%3},{%4,%5,%6,%7},{%8,%9},{%0,%1,%2,%3};"
        : "+f"(c[0]), "+f"(c[1]), "+f"(c[2]), "+f"(c[3])
        : "r"(a0), "r"(a1), "r"(a2), "r"(a3), "r"(b0), "r"(b1));
}

__device__ __forceinline__ void cp_async16(void* smem, const void* gmem, bool pred) {
    uint32_t s = (uint32_t)__cvta_generic_to_shared(smem);
    int src_bytes = pred ? 16 : 0;   // 0 -> zero-fill
    asm volatile("cp.async.cg.shared.global [%0], [%1], 16, %2;\n"
                 :: "r"(s), "l"(gmem), "r"(src_bytes));
}
__device__ __forceinline__ void cp_commit() { asm volatile("cp.async.commit_group;\n"); }
__device__ __forceinline__ void cp_wait2()  { asm volatile("cp.async.wait_group 2;\n"); }

__device__ __forceinline__ float apply_act(float v, const float* __restrict__ bias,
                                           const float* __restrict__ res,
                                           int gr, int gc, int N, int mode) {
    if (mode & 1)  v += bias[gc];
    if (mode & 2)  v += res[(size_t)gr * N + gc];
    if (mode & 4) {                       // gelu(tanh approx) via expf identity
        float x = v;
        float y = 0.7978845608028654f * (x + 0.044715f * x * x * x);
        y = fminf(fmaxf(y, -15.f), 15.f);
        float e = __expf(2.f * y);
        float th = (e - 1.f) / (e + 1.f);
        v = 0.5f * x * (1.f + th);
    }
    if (mode & 8)  v = fmaxf(v, 0.f);
    if (mode & 16) v = 1.f / (1.f + __expf(-v));
    return v;
}

// ------------------------- sparse embedding + pos embed -------------------------
__global__ void embed_kernel(const float* __restrict__ visits,
                             const float* __restrict__ vemb,
                             const float* __restrict__ pemb,
                             float* __restrict__ out)
{
    int row = blockIdx.x;            // b*Sz + s
    int s   = row % Sz;
    const float* vrow = visits + (size_t)row * Vz;
    int t = threadIdx.x;             // 256 threads
    float acc[3];
#pragma unroll
    for (int i = 0; i < 3; i++) acc[i] = pemb[s*Hz + t + i*256];

    __shared__ int   s_idx[256];
    __shared__ float s_val[256];
    __shared__ int   wcnt[8];

    int lane = t & 31, w = t >> 5;

    for (int base = 0; base < Vz; base += 256) {
        __syncthreads();
        int v = base + t;
        float val = (v < Vz) ? vrow[v] : 0.f;
        unsigned m = __ballot_sync(0xffffffffu, val != 0.f);
        if (lane == 0) wcnt[w] = __popc(m);
        __syncthreads();
        int off = 0;
#pragma unroll
        for (int i = 0; i < 8; i++) { if (i < w) off += wcnt[i]; }
        int cnt = 0;
#pragma unroll
        for (int i = 0; i < 8; i++) cnt += wcnt[i];
        if (val != 0.f) {
            int p = off + __popc(m & ((1u << lane) - 1u));
            s_idx[p] = v; s_val[p] = val;
        }
        __syncthreads();
        for (int j = 0; j < cnt; j++) {
            const float* er = vemb + (size_t)s_idx[j] * Hz;
            float vv = s_val[j];
#pragma unroll
            for (int i = 0; i < 3; i++) acc[i] += vv * er[t + i*256];
        }
    }
    float* orow = out + (size_t)row * Hz;
#pragma unroll
    for (int i = 0; i < 3; i++) orow[t + i*256] = acc[i];
}

// ------------------------- group norm (float4 vectorized) -------------------------
__global__ void groupnorm_kernel(const float* __restrict__ in, float* __restrict__ out,
                                 const float* __restrict__ w, const float* __restrict__ b)
{
    int bg = blockIdx.x;
    int bt = bg / Gz, g = bg % Gz;
    int t = threadIdx.x;             // 128 threads
    const int NELEM = Sz * CPG;      // 1152
    const int N4 = Sz * (CPG / 4);   // 288 float4s per group
    float sum = 0.f, sq = 0.f;
    for (int idx = t; idx < N4; idx += 128) {
        int s = idx / 6, c4 = idx % 6;
        float4 v = *(const float4*)&in[((size_t)bt*Sz + s)*Hz + g*CPG + c4*4];
        sum += v.x + v.y + v.z + v.w;
        sq  += v.x*v.x + v.y*v.y + v.z*v.z + v.w*v.w;
    }
    __shared__ float r1[128], r2[128];
    r1[t] = sum; r2[t] = sq; __syncthreads();
    for (int o = 64; o > 0; o >>= 1) {
        if (t < o) { r1[t] += r1[t+o]; r2[t] += r2[t+o]; }
        __syncthreads();
    }
    float mean = r1[0] / NELEM;
    float var  = r2[0] / NELEM - mean*mean;
    float inv  = rsqrtf(var + 1e-5f);
    for (int idx = t; idx < N4; idx += 128) {
        int s = idx / 6, c4 = idx % 6;
        int ch = g*CPG + c4*4;
        size_t off = ((size_t)bt*Sz + s)*Hz + ch;
        float4 v = *(const float4*)&in[off];
        float4 o4;
        o4.x = (v.x - mean) * inv * w[ch+0] + b[ch+0];
        o4.y = (v.y - mean) * inv * w[ch+1] + b[ch+1];
        o4.z = (v.z - mean) * inv * w[ch+2] + b[ch+2];
        o4.w = (v.w - mean) * inv * w[ch+3] + b[ch+3];
        *(float4*)&out[off] = o4;
    }
}

// ==================== 4-stage pipelined tf32 GEMM (single barrier per tile) ====================
#define SAST 20    // sA row stride (words): bank = (20*g + tig) % 32 bijective
#define SBST 136   // sB row stride (words): bank = (8*tig + g) % 32 bijective
#define STG  4

template<int BM>
__global__ __launch_bounds__(256, 2)
void gemm_tc_kernel(const float* __restrict__ A, const float* __restrict__ W,
                    const float* __restrict__ bias, const float* __restrict__ res,
                    float* __restrict__ C, int M, int N, int K, int mode)
{
    constexpr int MI = BM / 32;
    constexpr int A_ELE = BM * SAST;
    constexpr int B_ELE = 16 * SBST;
    extern __shared__ float smem[];
    float* sAb = smem;                 // [STG][BM][SAST]
    float* sBb = smem + STG * A_ELE;   // [STG][16][SBST]

    int t = threadIdx.x;
    int bm = blockIdx.y * BM;
    int bn = blockIdx.x * 128;
    int lane = t & 31, w = t >> 5;
    int wm = w & 1, wn = w >> 1;
    int m_base = wm * (BM / 2), n_base = wn * 32;
    int g = lane >> 2, tig = lane & 3;

    float acc[MI][4][4];
#pragma unroll
    for (int i = 0; i < MI; i++)
#pragma unroll
        for (int j = 0; j < 4; j++)
#pragma unroll
            for (int q = 0; q < 4; q++) acc[i][j][q] = 0.f;

    const int KT = K / 16;

    auto load_tile = [&](int st, int kt) {
        int k0 = kt * 16;
        float* sA = sAb + st * A_ELE;
        float* sB = sBb + st * B_ELE;
#pragma unroll
        for (int it = 0; it < BM / 64; it++) {
            int idx = it * 256 + t;
            int mr = idx >> 2;
            int kq = (idx & 3) * 4;
            cp_async16(sA + mr * SAST + kq, A + (size_t)(bm + mr) * K + k0 + kq, bm + mr < M);
        }
#pragma unroll
        for (int it = 0; it < 2; it++) {
            int idx = it * 256 + t;
            int kr = idx >> 5;
            int nq = (idx & 31) * 4;
            cp_async16(sB + kr * SBST + nq, W + (size_t)(k0 + kr) * N + bn + nq, true);
        }
    };

    // prefetch 3 stages
#pragma unroll
    for (int s = 0; s < 3; s++) { load_tile(s, s); cp_commit(); }

    for (int kt = 0; kt < KT; kt++) {
        cp_wait2();            // tile kt's group complete (this thread)
        __syncthreads();       // ...and everyone else's; also: all finished compute(kt-1)
        if (kt + 3 < KT) load_tile((kt + 3) & 3, kt + 3);
        cp_commit();

        const float* sA = sAb + (kt & 3) * A_ELE;
        const float* sB = sBb + (kt & 3) * B_ELE;
#pragma unroll
        for (int ks = 0; ks < 2; ks++) {
            int kk = ks * 8;
            uint32_t af[MI][4], bf[4][2];
#pragma unroll
            for (int mi = 0; mi < MI; mi++) {
                int m0 = m_base + mi * 16;
                af[mi][0] = __float_as_uint(sA[(m0 + g    ) * SAST + kk + tig    ]);
                af[mi][1] = __float_as_uint(sA[(m0 + g + 8) * SAST + kk + tig    ]);
                af[mi][2] = __float_as_uint(sA[(m0 + g    ) * SAST + kk + tig + 4]);
                af[mi][3] = __float_as_uint(sA[(m0 + g + 8) * SAST + kk + tig + 4]);
            }
#pragma unroll
            for (int ni = 0; ni < 4; ni++) {
                int n0 = n_base + ni * 8;
                bf[ni][0] = __float_as_uint(sB[(kk + tig    ) * SBST + n0 + g]);
                bf[ni][1] = __float_as_uint(sB[(kk + tig + 4) * SBST + n0 + g]);
            }
#pragma unroll
            for (int mi = 0; mi < MI; mi++)
#pragma unroll
                for (int ni = 0; ni < 4; ni++)
                    mma_tf32(acc[mi][ni], af[mi][0], af[mi][1], af[mi][2], af[mi][3],
                             bf[ni][0], bf[ni][1]);
        }
    }

    // epilogue
#pragma unroll
    for (int mi = 0; mi < MI; mi++) {
        int gr0 = bm + m_base + mi * 16 + g;
        int gr1 = gr0 + 8;
#pragma unroll
        for (int ni = 0; ni < 4; ni++) {
            int gc = bn + n_base + ni * 8 + 2 * tig;
            if (gr0 < M) {
                float v0 = apply_act(acc[mi][ni][0], bias, res, gr0, gc,     N, mode);
                float v1 = apply_act(acc[mi][ni][1], bias, res, gr0, gc + 1, N, mode);
                *(float2*)(C + (size_t)gr0 * N + gc) = make_float2(v0, v1);
            }
            if (gr1 < M) {
                float v2 = apply_act(acc[mi][ni][2], bias, res, gr1, gc,     N, mode);
                float v3 = apply_act(acc[mi][ni][3], bias, res, gr1, gc + 1, N, mode);
                *(float2*)(C + (size_t)gr1 * N + gc) = make_float2(v2, v3);
            }
        }
    }
}

// ======== 4-stage masked-transposed GEMM (single barrier per tile) ========
// C = act(A[M,K] @ (tril(W[N,K]))^T + bias); W[n,k] kept iff k <= n.
__global__ __launch_bounds__(256, 2)
void gemm_t_tc_kernel(const float* __restrict__ A, const float* __restrict__ Wr,
                      const float* __restrict__ bias,
                      float* __restrict__ C, int M, int N, int K, int mode)
{
    constexpr int BM = 128, MI = 4;
    constexpr int A_ELE = 128 * SAST;
    extern __shared__ float smem[];
    float* sAb  = smem;                 // [STG][128][SAST]
    float* sBTb = smem + STG * A_ELE;   // [STG][128][SAST]  ([n][k])

    int t = threadIdx.x;
    int bm = blockIdx.y * BM;
    int bn = blockIdx.x * 128;
    int lane = t & 31, w = t >> 5;
    int wm = w & 1, wn = w >> 1;
    int m_base = wm * 64, n_base = wn * 32;
    int g = lane >> 2, tig = lane & 3;
    const bool need_mask = (bn < K);    // uniform over CTA

    float acc[MI][4][4];
#pragma unroll
    for (int i = 0; i < MI; i++)
#pragma unroll
        for (int j = 0; j < 4; j++)
#pragma unroll
            for (int q = 0; q < 4; q++) acc[i][j][q] = 0.f;

    const int KT = K / 16;

    auto load_tile = [&](int st, int kt) {
        int k0 = kt * 16;
        float* sA  = sAb  + st * A_ELE;
        float* sBT = sBTb + st * A_ELE;
#pragma unroll
        for (int it = 0; it < 2; it++) {
            int idx = it * 256 + t;
            int mr = idx >> 2;
            int kq = (idx & 3) * 4;
            cp_async16(sA + mr * SAST + kq, A + (size_t)(bm + mr) * K + k0 + kq, bm + mr < M);
        }
#pragma unroll
        for (int it = 0; it < 2; it++) {
            int idx = it * 256 + t;
            int n  = idx >> 2;
            int kq = (idx & 3) * 4;
            cp_async16(sBT + n * SAST + kq, Wr + (size_t)(bn + n) * K + k0 + kq, true);
        }
    };

#pragma unroll
    for (int s = 0; s < 3; s++) { load_tile(s, s); cp_commit(); }

    for (int kt = 0; kt < KT; kt++) {
        cp_wait2();
        __syncthreads();
        if (kt + 3 < KT) load_tile((kt + 3) & 3, kt + 3);
        cp_commit();

        int k0 = kt * 16;
        const float* sA  = sAb  + (kt & 3) * A_ELE;
        const float* sBT = sBTb + (kt & 3) * A_ELE;
#pragma unroll
        for (int ks = 0; ks < 2; ks++) {
            int kk = ks * 8;
            uint32_t af[MI][4], bf[4][2];
#pragma unroll
            for (int mi = 0; mi < MI; mi++) {
                int m0 = m_base + mi * 16;
                af[mi][0] = __float_as_uint(sA[(m0 + g    ) * SAST + kk + tig    ]);
                af[mi][1] = __float_as_uint(sA[(m0 + g + 8) * SAST + kk + tig    ]);
                af[mi][2] = __float_as_uint(sA[(m0 + g    ) * SAST + kk + tig + 4]);
                af[mi][3] = __float_as_uint(sA[(m0 + g + 8) * SAST + kk + tig + 4]);
            }
            if (need_mask) {
                int kg0 = k0 + kk + tig;
                int kg1 = kg0 + 4;
#pragma unroll
                for (int ni = 0; ni < 4; ni++) {
                    int nl = n_base + ni * 8 + g;
                    int gn = bn + nl;
                    float b0 = sBT[nl * SAST + kk + tig    ];
                    float b1 = sBT[nl * SAST + kk + tig + 4];
                    bf[ni][0] = __float_as_uint(kg0 <= gn ? b0 : 0.f);
                    bf[ni][1] = __float_as_uint(kg1 <= gn ? b1 : 0.f);
                }
            } else {
#pragma unroll
                for (int ni = 0; ni < 4; ni++) {
                    int nl = n_base + ni * 8 + g;
                    bf[ni][0] = __float_as_uint(sBT[nl * SAST + kk + tig    ]);
                    bf[ni][1] = __float_as_uint(sBT[nl * SAST + kk + tig + 4]);
                }
            }
#pragma unroll
            for (int mi = 0; mi < MI; mi++)
#pragma unroll
                for (int ni = 0; ni < 4; ni++)
                    mma_tf32(acc[mi][ni], af[mi][0], af[mi][1], af[mi][2], af[mi][3],
                             bf[ni][0], bf[ni][1]);
        }
    }

#pragma unroll
    for (int mi = 0; mi < MI; mi++) {
        int gr0 = bm + m_base + mi * 16 + g;
        int gr1 = gr0 + 8;
#pragma unroll
        for (int ni = 0; ni < 4; ni++) {
            int gc = bn + n_base + ni * 8 + 2 * tig;
            if (gr0 < M) {
                float v0 = apply_act(acc[mi][ni][0], bias, nullptr, gr0, gc,     N, mode);
                float v1 = apply_act(acc[mi][ni][1], bias, nullptr, gr0, gc + 1, N, mode);
                *(float2*)(C + (size_t)gr0 * N + gc) = make_float2(v0, v1);
            }
            if (gr1 < M) {
                float v2 = apply_act(acc[mi][ni][2], bias, nullptr, gr1, gc,     N, mode);
                float v3 = apply_act(acc[mi][ni][3], bias, nullptr, gr1, gc + 1, N, mode);
                *(float2*)(C + (size_t)gr1 * N + gc) = make_float2(v2, v3);
            }
        }
    }
}

// ------------------------- attention: warp-parallel softmax, unrolled PV -------------------------
__global__ void attn_kernel(const float* __restrict__ qkv, float* __restrict__ out)
{
    int bh = blockIdx.x;
    int b = bh / NHz, hd = bh % NHz;
    __shared__ float sq[Sz][HDz+1], sk[Sz][HDz+1], sv[Sz][HDz+1];
    __shared__ float sp[8][Sz];
    int t = threadIdx.x;   // 256
    int lane = t & 31, wid = t >> 5;

    const float* base = qkv + (size_t)b * Sz * (3*Hz);
    for (int idx = t; idx < Sz*HDz; idx += 256) {
        int s = idx / HDz, d = idx % HDz;
        size_t o = (size_t)s * (3*Hz) + hd*HDz + d;
        sq[s][d] = base[o];
        sk[s][d] = base[o + Hz];
        sv[s][d] = base[o + 2*Hz];
    }
    __syncthreads();

    float* ob = out + (size_t)b * Sz * Hz + hd*HDz;

    for (int i = wid; i < Sz; i += 8) {
        int j1 = lane, j2 = lane + 32;
        float s1 = -1e30f, s2 = -1e30f;
        if (j1 <= i) {
            float a = 0.f;
#pragma unroll
            for (int d = 0; d < HDz; d++) a += sq[i][d] * sk[j1][d];
            s1 = a * 0.125f;
        }
        if (j2 <= i && j2 < Sz) {
            float a = 0.f;
#pragma unroll
            for (int d = 0; d < HDz; d++) a += sq[i][d] * sk[j2][d];
            s2 = a * 0.125f;
        }
        float mx = fmaxf(s1, s2);
#pragma unroll
        for (int o = 16; o > 0; o >>= 1) mx = fmaxf(mx, __shfl_xor_sync(0xffffffffu, mx, o));
        float e1 = (j1 <= i)            ? __expf(s1 - mx) : 0.f;
        float e2 = (j2 <= i && j2 < Sz) ? __expf(s2 - mx) : 0.f;
        float sum = e1 + e2;
#pragma unroll
        for (int o = 16; o > 0; o >>= 1) sum += __shfl_xor_sync(0xffffffffu, sum, o);
        float inv = 1.f / sum;
        sp[wid][j1] = e1 * inv;                 // zero for j1 > i
        if (j2 < Sz) sp[wid][j2] = e2 * inv;    // zero for j2 > i
        __syncwarp();

        // full fixed-trip unrolled PV: sp is exactly zero beyond row i
        float o1 = 0.f, o2 = 0.f;
#pragma unroll
        for (int j = 0; j < Sz; j++) {
            float p = sp[wid][j];
            o1 += p * sv[j][lane];
            o2 += p * sv[j][lane + 32];
        }
        ob[(size_t)i*Hz + lane]      = o1;
        ob[(size_t)i*Hz + lane + 32] = o2;
    }
}

// ------------------------- concat [h[:, :-1], h[:, 1:]] -------------------------
__global__ void concat_kernel(const float* __restrict__ x, float* __restrict__ cat)
{
    int idx = blockIdx.x * 256 + threadIdx.x;
    const int total = Bz*(Sz-1)*2*Hz;
    if (idx >= total) return;
    int c  = idx % (2*Hz);
    int bt = idx / (2*Hz);
    int tp = bt % (Sz-1), b = bt / (Sz-1);
    float v;
    if (c < Hz) v = x[((size_t)b*Sz + tp)*Hz + c];
    else        v = x[((size_t)b*Sz + tp + 1)*Hz + (c - Hz)];
    cat[idx] = v;
}

// ------------------------- launch -------------------------
extern "C" void kernel_launch(void* const* d_in, const int* in_sizes, int n_in,
                              void* d_out, int out_size)
{
    const float* visits = (const float*)d_in[0];
    const float* vemb   = (const float*)d_in[1];
    const float* pemb   = (const float*)d_in[2];
    const float* ln1w   = (const float*)d_in[3];
    const float* ln1b   = (const float*)d_in[4];
    const float* attnw  = (const float*)d_in[5];
    const float* attnb  = (const float*)d_in[6];
    const float* projw  = (const float*)d_in[7];
    const float* projb  = (const float*)d_in[8];
    const float* ln2w   = (const float*)d_in[9];
    const float* ln2b   = (const float*)d_in[10];
    const float* fcw    = (const float*)d_in[11];
    const float* fcb    = (const float*)d_in[12];
    const float* mprojw = (const float*)d_in[13];
    const float* mprojb = (const float*)d_in[14];
    const float* lnfw   = (const float*)d_in[15];
    const float* lnfb   = (const float*)d_in[16];
    const float* a1w    = (const float*)d_in[17];
    const float* a1b    = (const float*)d_in[18];
    const float* a2w    = (const float*)d_in[19];
    const float* a2b    = (const float*)d_in[20];
    float* out = (float*)d_out;

    float *ph, *px, *pqkv, *pa, *pmlp, *pcat, *pa1;
    cudaGetSymbolAddress((void**)&ph,   g_h);
    cudaGetSymbolAddress((void**)&px,   g_x);
    cudaGetSymbolAddress((void**)&pqkv, g_qkv);
    cudaGetSymbolAddress((void**)&pa,   g_a);
    cudaGetSymbolAddress((void**)&pmlp, g_mlp);
    cudaGetSymbolAddress((void**)&pcat, g_cat);
    cudaGetSymbolAddress((void**)&pa1,  g_a1);

    // dynamic smem sizes (4-stage)
    const int SM128 = STG * (128*SAST + 16*SBST) * 4;   // 75776 B
    const int SM64  = STG * ( 64*SAST + 16*SBST) * 4;   // 55296 B
    const int SMT   = STG * (128*SAST * 2) * 4;         // 81920 B
    cudaFuncSetAttribute(gemm_tc_kernel<128>, cudaFuncAttributeMaxDynamicSharedMemorySize, SM128);
    cudaFuncSetAttribute(gemm_tc_kernel<64>,  cudaFuncAttributeMaxDynamicSharedMemorySize, SM64);
    cudaFuncSetAttribute(gemm_t_tc_kernel,    cudaFuncAttributeMaxDynamicSharedMemorySize, SMT);

    const int M = Bz * Sz;   // 1536

    embed_kernel<<<Bz*Sz, 256>>>(visits, vemb, pemb, ph);

    for (int l = 0; l < NLz; l++) {
        groupnorm_kernel<<<Bz*Gz, 128>>>(ph, px, ln1w + l*Hz, ln1b + l*Hz);
        gemm_tc_kernel<128><<<dim3(3*Hz/128, M/128), 256, SM128>>>(
            px, attnw + (size_t)l*Hz*3*Hz, attnb + (size_t)l*3*Hz, nullptr,
            pqkv, M, 3*Hz, Hz, 1);
        attn_kernel<<<Bz*NHz, 256>>>(pqkv, pa);
        gemm_tc_kernel<64><<<dim3(Hz/128, M/64), 256, SM64>>>(
            pa, projw + (size_t)l*Hz*Hz, projb + (size_t)l*Hz, ph,
            ph, M, Hz, Hz, 1|2);
        groupnorm_kernel<<<Bz*Gz, 128>>>(ph, px, ln2w + l*Hz, ln2b + l*Hz);
        gemm_tc_kernel<128><<<dim3(4*Hz/128, M/128), 256, SM128>>>(
            px, fcw + (size_t)l*Hz*4*Hz, fcb + (size_t)l*4*Hz, nullptr,
            pmlp, M, 4*Hz, Hz, 1|4);
        gemm_tc_kernel<64><<<dim3(Hz/128, M/64), 256, SM64>>>(
            pmlp, mprojw + (size_t)l*4*Hz*Hz, mprojb + (size_t)l*Hz, ph,
            ph, M, Hz, 4*Hz, 1|2);
    }

    groupnorm_kernel<<<Bz*Gz, 128>>>(ph, px, lnfw, lnfb);

    const int Mh = Bz * (Sz - 1);  // 1504
    concat_kernel<<<(Mh*2*Hz + 255)/256, 256>>>(px, pcat);
    gemm_t_tc_kernel<<<dim3(2*Hz/128, (Mh + 127)/128), 256, SMT>>>(
        pcat, a1w, a1b, pa1, Mh, 2*Hz, 2*Hz, 1|8);
    gemm_t_tc_kernel<<<dim3(CVz/128, (Mh + 127)/128), 256, SMT>>>(
        pa1, a2w, a2b, out, Mh, CVz, 2*Hz, 1|16);
}